// round 2
// baseline (speedup 1.0000x reference)
#include <cuda_runtime.h>
#include <math.h>
#include <stdint.h>

// Problem constants
#define BB 4
#define CIN 256
#define CI 128
#define NN 4096          // H*W = 64*64
#define CP 384           // 3*CI projection channels
#define COUT 256
#define BN_EPS 1e-5f

// Scratch (static device globals; allocation APIs are forbidden)
__device__ float d_proj[CP * BB * NN];     // [m][b][n], m: 0..127=g, 128..255=theta, 256..383=phi
__device__ float d_pscale[CP];
__device__ float d_pshift[CP];
__device__ float d_y[BB * CI * NN];        // [b][c][n]
__device__ float d_z[COUT * BB * NN];      // [o][b][n]  (channel-contiguous for stats)
__device__ float d_zscale[COUT];
__device__ float d_zshift[COUT];

// ---------------- packed f32x2 helpers ----------------
__device__ __forceinline__ unsigned long long f2ull(float2 v) {
    unsigned long long u;
    memcpy(&u, &v, 8);
    return u;
}
__device__ __forceinline__ float2 ull2f(unsigned long long u) {
    float2 v;
    memcpy(&v, &u, 8);
    return v;
}
__device__ __forceinline__ float2 ffma2(float2 a, float2 b, float2 c) {
    unsigned long long r;
    asm("fma.rn.f32x2 %0, %1, %2, %3;"
        : "=l"(r) : "l"(f2ull(a)), "l"(f2ull(b)), "l"(f2ull(c)));
    return ull2f(r);
}
__device__ __forceinline__ float2 fmul2(float2 a, float2 b) {
    unsigned long long r;
    asm("mul.rn.f32x2 %0, %1, %2;"
        : "=l"(r) : "l"(f2ull(a)), "l"(f2ull(b)));
    return ull2f(r);
}

// ---------------- Kernel 1: fused projection GEMM ----------------
// proj[m][b][n] = sum_k Wsel[m][k] * x[b][k][n] + bsel[m]
// grid (N/64, CP/64, B), 256 threads, 64x64 tile, 4x4 microtile.
__global__ __launch_bounds__(256) void proj_gemm_kernel(
    const float* __restrict__ x,
    const float* __restrict__ gw, const float* __restrict__ gb,
    const float* __restrict__ thw, const float* __restrict__ thb,
    const float* __restrict__ phw, const float* __restrict__ phb)
{
    __shared__ float As[16 * 64];
    __shared__ float Bs[16 * 64];
    const int t = threadIdx.x;
    const int tx = t & 15, ty = t >> 4;
    const int b = blockIdx.z;
    const int m0 = blockIdx.y * 64;
    const int n0 = blockIdx.x * 64;

    float acc[4][4];
#pragma unroll
    for (int i = 0; i < 4; i++)
#pragma unroll
        for (int j = 0; j < 4; j++) acc[i][j] = 0.0f;

    for (int k0 = 0; k0 < CIN; k0 += 16) {
#pragma unroll
        for (int pp = 0; pp < 4; pp++) {
            int idx = pp * 256 + t;
            int mm = idx & 63, kk = idx >> 6;
            int m = m0 + mm;
            const float* wr;
            if (m < 128)      wr = gw + m * CIN;
            else if (m < 256) wr = thw + (m - 128) * CIN;
            else              wr = phw + (m - 256) * CIN;
            As[kk * 64 + mm] = wr[k0 + kk];
        }
#pragma unroll
        for (int pp = 0; pp < 4; pp++) {
            int idx = pp * 256 + t;
            int nn = idx & 63, kk = idx >> 6;
            Bs[kk * 64 + nn] = x[(b * CIN + k0 + kk) * NN + n0 + nn];
        }
        __syncthreads();
#pragma unroll
        for (int kk = 0; kk < 16; kk++) {
            float4 a4 = *(const float4*)&As[kk * 64 + ty * 4];
            float4 b4 = *(const float4*)&Bs[kk * 64 + tx * 4];
            float av[4] = {a4.x, a4.y, a4.z, a4.w};
            float bv[4] = {b4.x, b4.y, b4.z, b4.w};
#pragma unroll
            for (int i = 0; i < 4; i++)
#pragma unroll
                for (int j = 0; j < 4; j++)
                    acc[i][j] = fmaf(av[i], bv[j], acc[i][j]);
        }
        __syncthreads();
    }
#pragma unroll
    for (int i = 0; i < 4; i++) {
        int m = m0 + ty * 4 + i;
        float bias;
        if (m < 128)      bias = gb[m];
        else if (m < 256) bias = thb[m - 128];
        else              bias = phb[m - 256];
        float4 o;
        o.x = acc[i][0] + bias;
        o.y = acc[i][1] + bias;
        o.z = acc[i][2] + bias;
        o.w = acc[i][3] + bias;
        *(float4*)&d_proj[m * (BB * NN) + b * NN + n0 + tx * 4] = o;
    }
}

// ---------------- Kernel 2: BN stats for projections ----------------
__global__ __launch_bounds__(256) void bn_stats_proj_kernel(
    const float* __restrict__ g_gamma, const float* __restrict__ g_beta,
    const float* __restrict__ th_gamma, const float* __restrict__ th_beta,
    const float* __restrict__ ph_gamma, const float* __restrict__ ph_beta)
{
    __shared__ double ssum[256];
    __shared__ double ssq[256];
    const int ch = blockIdx.x;
    const int t = threadIdx.x;
    const float* base = d_proj + ch * (BB * NN);
    double s = 0.0, q = 0.0;
    for (int i = t; i < BB * NN; i += 256) {
        float v = base[i];
        s += (double)v;
        q += (double)v * (double)v;
    }
    ssum[t] = s; ssq[t] = q;
    __syncthreads();
    for (int off = 128; off > 0; off >>= 1) {
        if (t < off) { ssum[t] += ssum[t + off]; ssq[t] += ssq[t + off]; }
        __syncthreads();
    }
    if (t == 0) {
        double mean = ssum[0] / (double)(BB * NN);
        double var = ssq[0] / (double)(BB * NN) - mean * mean;
        float gamma, beta;
        if (ch < 128)      { gamma = g_gamma[ch];        beta = g_beta[ch]; }
        else if (ch < 256) { gamma = th_gamma[ch - 128]; beta = th_beta[ch - 128]; }
        else               { gamma = ph_gamma[ch - 256]; beta = ph_beta[ch - 256]; }
        float sc = gamma / sqrtf((float)var + BN_EPS);
        d_pscale[ch] = sc;
        d_pshift[ch] = beta - (float)mean * sc;
    }
}

// ---------------- Kernel 3: fused flash attention (fp32, f32x2 FMA) ----------------
// Q tile = 128 rows, K/V tile = 64. Grid (N/128, B), 256 threads as 16x16.
// Each thread: 8 query rows (i = ty*8+r), 4 S cols (j = tx*4..), 8 O channels (c = tx*8..).
#define SM_QS 0
#define SM_KS 16384                 // 128*68
#define SM_GS (16384 + 8704)        // 64*132
#define SM_PS (16384 + 8704 + 8448) // 128*68
#define ATTN_SMEM_FLOATS (16384 + 8704 + 8448 + 8704)

__global__ __launch_bounds__(256, 1) void attn_kernel()
{
    extern __shared__ float sm[];
    float* Qs = sm + SM_QS;
    float* Ks = sm + SM_KS;
    float* Gs = sm + SM_GS;
    float* Ps = sm + SM_PS;

    const int t = threadIdx.x;
    const int tx = t & 15, ty = t >> 4;
    const int b = blockIdx.y;
    const int n0 = blockIdx.x * 128;

    // Fill Q (theta, BN applied): Qs[c][i], c=0..127, i=0..127
#pragma unroll 1
    for (int pp = 0; pp < 64; pp++) {
        int idx = pp * 256 + t;
        int c = idx >> 7, i = idx & 127;
        float v = d_proj[(128 + c) * (BB * NN) + b * NN + n0 + i];
        Qs[c * 128 + i] = v * d_pscale[128 + c] + d_pshift[128 + c];
    }

    float2 O[8][4];
    float m_r[8], l_r[8];
#pragma unroll
    for (int r = 0; r < 8; r++) {
        m_r[r] = -INFINITY; l_r[r] = 0.0f;
#pragma unroll
        for (int cc = 0; cc < 4; cc++) O[r][cc] = make_float2(0.0f, 0.0f);
    }

    for (int kt = 0; kt < 64; kt++) {
        const int m0 = kt * 64;
        // Fill K (phi) [c][68-padded] and G [j][132-padded], BN applied
#pragma unroll 1
        for (int pp = 0; pp < 32; pp++) {
            int idx = pp * 256 + t;
            int c = idx >> 6, j = idx & 63;
            float kv = d_proj[(256 + c) * (BB * NN) + b * NN + m0 + j];
            Ks[c * 68 + j] = kv * d_pscale[256 + c] + d_pshift[256 + c];
            float gv = d_proj[c * (BB * NN) + b * NN + m0 + j];
            Gs[j * 132 + c] = gv * d_pscale[c] + d_pshift[c];
        }
        __syncthreads();

        // S = Q^T K : s[r][pair], pairs along j
        float2 s[8][2];
#pragma unroll
        for (int r = 0; r < 8; r++) { s[r][0] = make_float2(0.f, 0.f); s[r][1] = make_float2(0.f, 0.f); }

#pragma unroll 4
        for (int c = 0; c < 128; c++) {
            float qa[8];
            *(float4*)qa       = *(const float4*)(Qs + c * 128 + ty * 8);
            *(float4*)(qa + 4) = *(const float4*)(Qs + c * 128 + ty * 8 + 4);
            float4 k4 = *(const float4*)(Ks + c * 68 + tx * 4);
            float2 k0 = make_float2(k4.x, k4.y);
            float2 k1 = make_float2(k4.z, k4.w);
#pragma unroll
            for (int r = 0; r < 8; r++) {
                float2 q2 = make_float2(qa[r], qa[r]);
                s[r][0] = ffma2(q2, k0, s[r][0]);
                s[r][1] = ffma2(q2, k1, s[r][1]);
            }
        }

        // Online softmax per row; P -> smem
#pragma unroll
        for (int r = 0; r < 8; r++) {
            float mx = fmaxf(fmaxf(s[r][0].x, s[r][0].y), fmaxf(s[r][1].x, s[r][1].y));
            mx = fmaxf(mx, __shfl_xor_sync(0xffffffffu, mx, 1));
            mx = fmaxf(mx, __shfl_xor_sync(0xffffffffu, mx, 2));
            mx = fmaxf(mx, __shfl_xor_sync(0xffffffffu, mx, 4));
            mx = fmaxf(mx, __shfl_xor_sync(0xffffffffu, mx, 8));
            float mn = fmaxf(m_r[r], mx);
            float corr = __expf(m_r[r] - mn);
            m_r[r] = mn;
            float p0 = __expf(s[r][0].x - mn);
            float p1 = __expf(s[r][0].y - mn);
            float p2 = __expf(s[r][1].x - mn);
            float p3 = __expf(s[r][1].y - mn);
            float rs = (p0 + p1) + (p2 + p3);
            rs += __shfl_xor_sync(0xffffffffu, rs, 1);
            rs += __shfl_xor_sync(0xffffffffu, rs, 2);
            rs += __shfl_xor_sync(0xffffffffu, rs, 4);
            rs += __shfl_xor_sync(0xffffffffu, rs, 8);
            l_r[r] = l_r[r] * corr + rs;
            float2 c2 = make_float2(corr, corr);
#pragma unroll
            for (int cc = 0; cc < 4; cc++) O[r][cc] = fmul2(O[r][cc], c2);
            float4 pv4 = make_float4(p0, p1, p2, p3);
            *(float4*)(Ps + (ty * 8 + r) * 68 + tx * 4) = pv4;
        }
        __syncthreads();

        // O += P * G^T
#pragma unroll 1
        for (int jc = 0; jc < 16; jc++) {
            const int j0 = jc * 4;
            float2 g[4][4];
#pragma unroll
            for (int jj = 0; jj < 4; jj++) {
                float4 ga = *(const float4*)(Gs + (j0 + jj) * 132 + tx * 8);
                float4 gbv = *(const float4*)(Gs + (j0 + jj) * 132 + tx * 8 + 4);
                g[jj][0] = make_float2(ga.x, ga.y);
                g[jj][1] = make_float2(ga.z, ga.w);
                g[jj][2] = make_float2(gbv.x, gbv.y);
                g[jj][3] = make_float2(gbv.z, gbv.w);
            }
#pragma unroll
            for (int r = 0; r < 8; r++) {
                float pa[4];
                *(float4*)pa = *(const float4*)(Ps + (ty * 8 + r) * 68 + j0);
#pragma unroll
                for (int jj = 0; jj < 4; jj++) {
                    float2 pv = make_float2(pa[jj], pa[jj]);
#pragma unroll
                    for (int cc = 0; cc < 4; cc++)
                        O[r][cc] = ffma2(pv, g[jj][cc], O[r][cc]);
                }
            }
        }
        __syncthreads();
    }

    // Epilogue: O /= l, bounce through Qs for coalesced global writes
#pragma unroll
    for (int r = 0; r < 8; r++) {
        float inv = 1.0f / l_r[r];
        int i = ty * 8 + r;
#pragma unroll
        for (int cc = 0; cc < 4; cc++) {
            int c0 = tx * 8 + cc * 2;
            Qs[c0 * 128 + i]       = O[r][cc].x * inv;
            Qs[(c0 + 1) * 128 + i] = O[r][cc].y * inv;
        }
    }
    __syncthreads();
#pragma unroll 1
    for (int pp = 0; pp < 64; pp++) {
        int idx = pp * 256 + t;
        int c = idx >> 7, i = idx & 127;
        d_y[(b * CI + c) * NN + n0 + i] = Qs[c * 128 + i];
    }
}

// ---------------- Kernel 4: W GEMM + bias + residual ----------------
// z[o][b][n] = sum_c W_w[o][c]*y[b][c][n] + W_b[o] + x[b][o][n]
__global__ __launch_bounds__(256) void wgemm_kernel(
    const float* __restrict__ x,
    const float* __restrict__ Ww, const float* __restrict__ Wb)
{
    __shared__ float As[16 * 64];
    __shared__ float Bs[16 * 64];
    const int t = threadIdx.x;
    const int tx = t & 15, ty = t >> 4;
    const int b = blockIdx.z;
    const int o0 = blockIdx.y * 64;
    const int n0 = blockIdx.x * 64;

    float acc[4][4];
#pragma unroll
    for (int i = 0; i < 4; i++)
#pragma unroll
        for (int j = 0; j < 4; j++) acc[i][j] = 0.0f;

    for (int k0 = 0; k0 < CI; k0 += 16) {
#pragma unroll
        for (int pp = 0; pp < 4; pp++) {
            int idx = pp * 256 + t;
            int mm = idx & 63, kk = idx >> 6;
            As[kk * 64 + mm] = Ww[(o0 + mm) * CI + k0 + kk];
        }
#pragma unroll
        for (int pp = 0; pp < 4; pp++) {
            int idx = pp * 256 + t;
            int nn = idx & 63, kk = idx >> 6;
            Bs[kk * 64 + nn] = d_y[(b * CI + k0 + kk) * NN + n0 + nn];
        }
        __syncthreads();
#pragma unroll
        for (int kk = 0; kk < 16; kk++) {
            float4 a4 = *(const float4*)&As[kk * 64 + ty * 4];
            float4 b4 = *(const float4*)&Bs[kk * 64 + tx * 4];
            float av[4] = {a4.x, a4.y, a4.z, a4.w};
            float bv[4] = {b4.x, b4.y, b4.z, b4.w};
#pragma unroll
            for (int i = 0; i < 4; i++)
#pragma unroll
                for (int j = 0; j < 4; j++)
                    acc[i][j] = fmaf(av[i], bv[j], acc[i][j]);
        }
        __syncthreads();
    }
#pragma unroll
    for (int i = 0; i < 4; i++) {
        int o = o0 + ty * 4 + i;
        float bias = Wb[o];
        float4 xr = *(const float4*)&x[(b * COUT + o) * NN + n0 + tx * 4];
        float4 zo;
        zo.x = acc[i][0] + bias + xr.x;
        zo.y = acc[i][1] + bias + xr.y;
        zo.z = acc[i][2] + bias + xr.z;
        zo.w = acc[i][3] + bias + xr.w;
        *(float4*)&d_z[o * (BB * NN) + b * NN + n0 + tx * 4] = zo;
    }
}

// ---------------- Kernel 5: BN stats for z ----------------
__global__ __launch_bounds__(256) void bn_stats_z_kernel(
    const float* __restrict__ bn_gamma, const float* __restrict__ bn_beta)
{
    __shared__ double ssum[256];
    __shared__ double ssq[256];
    const int ch = blockIdx.x;
    const int t = threadIdx.x;
    const float* base = d_z + ch * (BB * NN);
    double s = 0.0, q = 0.0;
    for (int i = t; i < BB * NN; i += 256) {
        float v = base[i];
        s += (double)v;
        q += (double)v * (double)v;
    }
    ssum[t] = s; ssq[t] = q;
    __syncthreads();
    for (int off = 128; off > 0; off >>= 1) {
        if (t < off) { ssum[t] += ssum[t + off]; ssq[t] += ssq[t + off]; }
        __syncthreads();
    }
    if (t == 0) {
        double mean = ssum[0] / (double)(BB * NN);
        double var = ssq[0] / (double)(BB * NN) - mean * mean;
        float sc = bn_gamma[ch] / sqrtf((float)var + BN_EPS);
        d_zscale[ch] = sc;
        d_zshift[ch] = bn_beta[ch] - (float)mean * sc;
    }
}

// ---------------- Kernel 6: final normalize, layout to (B,C,H,W) ----------------
__global__ __launch_bounds__(256) void finalize_kernel(float* __restrict__ out)
{
    int idx = blockIdx.x * 256 + threadIdx.x;  // over COUT*BB*NN
    int o = idx >> 14;            // / (BB*NN)
    int rem = idx & 16383;
    int b = rem >> 12;
    int n = rem & 4095;
    out[(b * COUT + o) * NN + n] = d_z[idx] * d_zscale[o] + d_zshift[o];
}

// ---------------- host launcher ----------------
extern "C" void kernel_launch(void* const* d_in, const int* in_sizes, int n_in,
                              void* d_out, int out_size)
{
    const float* x        = (const float*)d_in[0];
    const float* g_w      = (const float*)d_in[1];
    const float* g_b      = (const float*)d_in[2];
    const float* g_gamma  = (const float*)d_in[3];
    const float* g_beta   = (const float*)d_in[4];
    const float* th_w     = (const float*)d_in[5];
    const float* th_b     = (const float*)d_in[6];
    const float* th_gamma = (const float*)d_in[7];
    const float* th_beta  = (const float*)d_in[8];
    const float* ph_w     = (const float*)d_in[9];
    const float* ph_b     = (const float*)d_in[10];
    const float* ph_gamma = (const float*)d_in[11];
    const float* ph_beta  = (const float*)d_in[12];
    const float* W_w      = (const float*)d_in[13];
    const float* W_b      = (const float*)d_in[14];
    const float* bn_gamma = (const float*)d_in[15];
    const float* bn_beta  = (const float*)d_in[16];
    float* out = (float*)d_out;

    const int attn_smem = ATTN_SMEM_FLOATS * 4;  // 168960 B
    cudaFuncSetAttribute(attn_kernel, cudaFuncAttributeMaxDynamicSharedMemorySize, attn_smem);

    proj_gemm_kernel<<<dim3(NN / 64, CP / 64, BB), 256>>>(x, g_w, g_b, th_w, th_b, ph_w, ph_b);
    bn_stats_proj_kernel<<<CP, 256>>>(g_gamma, g_beta, th_gamma, th_beta, ph_gamma, ph_beta);
    attn_kernel<<<dim3(NN / 128, BB), 256, attn_smem>>>();
    wgemm_kernel<<<dim3(NN / 64, COUT / 64, BB), 256>>>(x, W_w, W_b);
    bn_stats_z_kernel<<<COUT, 256>>>(bn_gamma, bn_beta);
    finalize_kernel<<<(COUT * BB * NN) / 256, 256>>>(out);
}

// round 4
// speedup vs baseline: 2.7352x; 2.7352x over previous
#include <cuda_runtime.h>
#include <cuda_fp16.h>
#include <math.h>
#include <stdint.h>

// Problem constants
#define BB 4
#define CIN 256
#define CI 128
#define NN 4096          // H*W = 64*64
#define CP 384           // 3*CI projection channels
#define COUT 256
#define BN_EPS 1e-5f
#define NTILES 32        // NN / 128 key tiles

// Scratch (static device globals; allocation APIs are forbidden)
__device__ float d_proj[CP * BB * NN];     // [m][b][n], m: 0..127=g, 128..255=theta, 256..383=phi
__device__ float d_pscale[CP];
__device__ float d_pshift[CP];
__device__ float d_y[BB * CI * NN];        // [b][c][n]
__device__ float d_z[COUT * BB * NN];      // [o][b][n]
__device__ float d_zscale[COUT];
__device__ float d_zshift[COUT];

// fp16 hi/lo split operands for tensor-core attention
__device__ __half d_th_hi[BB * NN * CI];   // theta^T  [b][n][c]
__device__ __half d_th_lo[BB * NN * CI];
__device__ __half d_ph_hi[BB * NN * CI];   // phi^T    [b][n][c]
__device__ __half d_ph_lo[BB * NN * CI];
__device__ __half d_g_hi[BB * CI * NN];    // g        [b][c][n]
__device__ __half d_g_lo[BB * CI * NN];

// ======================= helpers =======================
__device__ __forceinline__ uint32_t smem_u32(const void* p) {
    uint32_t a;
    asm("{ .reg .u64 t; cvta.to.shared.u64 t, %1; cvt.u32.u64 %0, t; }" : "=r"(a) : "l"(p));
    return a;
}

// ldmatrix x4 (non-trans)
__device__ __forceinline__ void ldsm4(uint32_t& r0, uint32_t& r1, uint32_t& r2, uint32_t& r3,
                                      uint32_t addr) {
    asm volatile("ldmatrix.sync.aligned.m8n8.x4.shared.b16 {%0,%1,%2,%3}, [%4];"
                 : "=r"(r0), "=r"(r1), "=r"(r2), "=r"(r3) : "r"(addr));
}

// mma.sync m16n8k16 row.col, fp16 in, fp32 accum
__device__ __forceinline__ void mma16816(float* d, uint32_t a0, uint32_t a1, uint32_t a2, uint32_t a3,
                                         uint32_t b0, uint32_t b1) {
    asm volatile(
        "mma.sync.aligned.m16n8k16.row.col.f32.f16.f16.f32 "
        "{%0,%1,%2,%3}, {%4,%5,%6,%7}, {%8,%9}, {%0,%1,%2,%3};"
        : "+f"(d[0]), "+f"(d[1]), "+f"(d[2]), "+f"(d[3])
        : "r"(a0), "r"(a1), "r"(a2), "r"(a3), "r"(b0), "r"(b1));
}

// swizzled tile address: 128 rows x 128 halfs (256B rows), 16B chunks XOR'd with row&7
__device__ __forceinline__ uint32_t sw_addr(uint32_t base, int row, int chunk) {
    return base + (uint32_t)row * 256u + (uint32_t)((chunk ^ (row & 7)) << 4);
}

// ---------------- Kernel 1: fused projection GEMM ----------------
__global__ __launch_bounds__(256) void proj_gemm_kernel(
    const float* __restrict__ x,
    const float* __restrict__ gw, const float* __restrict__ gb,
    const float* __restrict__ thw, const float* __restrict__ thb,
    const float* __restrict__ phw, const float* __restrict__ phb)
{
    __shared__ float As[16 * 64];
    __shared__ float Bs[16 * 64];
    const int t = threadIdx.x;
    const int tx = t & 15, ty = t >> 4;
    const int b = blockIdx.z;
    const int m0 = blockIdx.y * 64;
    const int n0 = blockIdx.x * 64;

    float acc[4][4];
#pragma unroll
    for (int i = 0; i < 4; i++)
#pragma unroll
        for (int j = 0; j < 4; j++) acc[i][j] = 0.0f;

    for (int k0 = 0; k0 < CIN; k0 += 16) {
#pragma unroll
        for (int pp = 0; pp < 4; pp++) {
            int idx = pp * 256 + t;
            int mm = idx & 63, kk = idx >> 6;
            int m = m0 + mm;
            const float* wr;
            if (m < 128)      wr = gw + m * CIN;
            else if (m < 256) wr = thw + (m - 128) * CIN;
            else              wr = phw + (m - 256) * CIN;
            As[kk * 64 + mm] = wr[k0 + kk];
        }
#pragma unroll
        for (int pp = 0; pp < 4; pp++) {
            int idx = pp * 256 + t;
            int nn = idx & 63, kk = idx >> 6;
            Bs[kk * 64 + nn] = x[(b * CIN + k0 + kk) * NN + n0 + nn];
        }
        __syncthreads();
#pragma unroll
        for (int kk = 0; kk < 16; kk++) {
            float4 a4 = *(const float4*)&As[kk * 64 + ty * 4];
            float4 b4 = *(const float4*)&Bs[kk * 64 + tx * 4];
            float av[4] = {a4.x, a4.y, a4.z, a4.w};
            float bv[4] = {b4.x, b4.y, b4.z, b4.w};
#pragma unroll
            for (int i = 0; i < 4; i++)
#pragma unroll
                for (int j = 0; j < 4; j++)
                    acc[i][j] = fmaf(av[i], bv[j], acc[i][j]);
        }
        __syncthreads();
    }
#pragma unroll
    for (int i = 0; i < 4; i++) {
        int m = m0 + ty * 4 + i;
        float bias;
        if (m < 128)      bias = gb[m];
        else if (m < 256) bias = thb[m - 128];
        else              bias = phb[m - 256];
        float4 o;
        o.x = acc[i][0] + bias;
        o.y = acc[i][1] + bias;
        o.z = acc[i][2] + bias;
        o.w = acc[i][3] + bias;
        *(float4*)&d_proj[m * (BB * NN) + b * NN + n0 + tx * 4] = o;
    }
}

// ---------------- Kernel 2: BN stats for projections ----------------
__global__ __launch_bounds__(256) void bn_stats_proj_kernel(
    const float* __restrict__ g_gamma, const float* __restrict__ g_beta,
    const float* __restrict__ th_gamma, const float* __restrict__ th_beta,
    const float* __restrict__ ph_gamma, const float* __restrict__ ph_beta)
{
    __shared__ double ssum[256];
    __shared__ double ssq[256];
    const int ch = blockIdx.x;
    const int t = threadIdx.x;
    const float* base = d_proj + ch * (BB * NN);
    double s = 0.0, q = 0.0;
    for (int i = t; i < BB * NN; i += 256) {
        float v = base[i];
        s += (double)v;
        q += (double)v * (double)v;
    }
    ssum[t] = s; ssq[t] = q;
    __syncthreads();
    for (int off = 128; off > 0; off >>= 1) {
        if (t < off) { ssum[t] += ssum[t + off]; ssq[t] += ssq[t + off]; }
        __syncthreads();
    }
    if (t == 0) {
        double mean = ssum[0] / (double)(BB * NN);
        double var = ssq[0] / (double)(BB * NN) - mean * mean;
        float gamma, beta;
        if (ch < 128)      { gamma = g_gamma[ch];        beta = g_beta[ch]; }
        else if (ch < 256) { gamma = th_gamma[ch - 128]; beta = th_beta[ch - 128]; }
        else               { gamma = ph_gamma[ch - 256]; beta = ph_beta[ch - 256]; }
        float sc = gamma / sqrtf((float)var + BN_EPS);
        d_pscale[ch] = sc;
        d_pshift[ch] = beta - (float)mean * sc;
    }
}

// ---------------- Kernel 2b: prep theta/phi -> fp16 hi/lo, transposed to [b][n][c] ----------------
__global__ __launch_bounds__(256) void prep_qk_kernel()
{
    __shared__ float tile[32][33];
    const int t = threadIdx.x;
    const int tx = t & 31, ty = t >> 5;
    const int sel = blockIdx.z >> 2;      // 0: theta, 1: phi
    const int b = blockIdx.z & 3;
    const int c0 = blockIdx.y * 32;
    const int n0 = blockIdx.x * 32;
    const int chbase = 128 + sel * 128;
#pragma unroll
    for (int i = 0; i < 4; i++) {
        int c = c0 + ty + i * 8;
        float v = d_proj[(size_t)(chbase + c) * (BB * NN) + (size_t)b * NN + n0 + tx];
        tile[ty + i * 8][tx] = v * d_pscale[chbase + c] + d_pshift[chbase + c];
    }
    __syncthreads();
    __half* hi = sel ? d_ph_hi : d_th_hi;
    __half* lo = sel ? d_ph_lo : d_th_lo;
#pragma unroll
    for (int i = 0; i < 4; i++) {
        int n = n0 + ty + i * 8;
        float v = tile[tx][ty + i * 8];
        __half h = __float2half_rn(v);
        __half l = __float2half_rn(v - __half2float(h));
        size_t idx = (size_t)(b * NN + n) * CI + c0 + tx;
        hi[idx] = h;
        lo[idx] = l;
    }
}

// ---------------- Kernel 2c: prep g -> fp16 hi/lo, [b][c][n] ----------------
__global__ __launch_bounds__(256) void prep_g_kernel()
{
    int i = blockIdx.x * 256 + threadIdx.x;  // over BB*CI*NN/4
    int n4 = i & (NN / 4 - 1);
    int rest = i / (NN / 4);
    int c = rest & (CI - 1);
    int b = rest >> 7;
    float4 v = *(const float4*)&d_proj[(size_t)c * (BB * NN) + (size_t)b * NN + n4 * 4];
    float sc = d_pscale[c], sh = d_pshift[c];
    float a0 = v.x * sc + sh, a1 = v.y * sc + sh, a2 = v.z * sc + sh, a3 = v.w * sc + sh;
    __half h0 = __float2half_rn(a0), h1 = __float2half_rn(a1);
    __half h2 = __float2half_rn(a2), h3 = __float2half_rn(a3);
    __half l0 = __float2half_rn(a0 - __half2float(h0));
    __half l1 = __float2half_rn(a1 - __half2float(h1));
    __half l2 = __float2half_rn(a2 - __half2float(h2));
    __half l3 = __float2half_rn(a3 - __half2float(h3));
    size_t base = (size_t)(b * CI + c) * NN + n4 * 4;
    *(__half2*)&d_g_hi[base]     = __halves2half2(h0, h1);
    *(__half2*)&d_g_hi[base + 2] = __halves2half2(h2, h3);
    *(__half2*)&d_g_lo[base]     = __halves2half2(l0, l1);
    *(__half2*)&d_g_lo[base + 2] = __halves2half2(l2, l3);
}

// ---------------- Kernel 3: mma.sync flash attention (fp16 hi/lo split) ----------------
// Grid (32 q-tiles, 4 b), 256 threads = 8 warps, warp w owns q rows [16w,16w+16).
// SMEM: six 128x128 fp16 tiles (32KB each, XOR-swizzled 256B rows): Qhi,Qlo,Khi,Klo,Ghi,Glo.
#define OFF_QHI 0
#define OFF_QLO 32768
#define OFF_KHI 65536
#define OFF_KLO 98304
#define OFF_GHI 131072
#define OFF_GLO 163840
#define OFF_EPI 65536      // epilogue reuses K/G region: 128*129*4 = 66048 B
#define ATTN_SMEM_BYTES 196608

// cooperative load of a 128x128 half tile into swizzled smem
__device__ __forceinline__ void load_tile(uint32_t dst, const __half* __restrict__ src,
                                          int row_stride) {
    const int t = threadIdx.x;
#pragma unroll
    for (int i = 0; i < 8; i++) {
        int cid = i * 256 + t;
        int row = cid >> 4, c = cid & 15;
        uint4 v = *(const uint4*)(src + (size_t)row * row_stride + c * 8);
        uint32_t a = sw_addr(dst, row, c);
        asm volatile("st.shared.v4.b32 [%0], {%1, %2, %3, %4};"
                     :: "r"(a), "r"(v.x), "r"(v.y), "r"(v.z), "r"(v.w));
    }
}

__global__ __launch_bounds__(256, 1) void attn_mma_kernel()
{
    extern __shared__ char smem[];
    const uint32_t sb = smem_u32(smem);
    const int tid = threadIdx.x;
    const int lane = tid & 31;
    const int w = tid >> 5;
    const int b = blockIdx.y;
    const int n0 = blockIdx.x * 128;

    // persistent Q tiles
    load_tile(sb + OFF_QHI, d_th_hi + (size_t)(b * NN + n0) * CI, CI);
    load_tile(sb + OFF_QLO, d_th_lo + (size_t)(b * NN + n0) * CI, CI);

    const int frow = lane & 15;       // ldmatrix row within 16-block
    const int fhalf = lane >> 4;      // k-half selector
    const int arow = w * 16 + frow;   // Q row for this warp

    float o[16][4];
#pragma unroll
    for (int nf = 0; nf < 16; nf++)
#pragma unroll
        for (int j = 0; j < 4; j++) o[nf][j] = 0.0f;
    float mr0 = -INFINITY, mr1 = -INFINITY, lr0 = 0.0f, lr1 = 0.0f;

    for (int t = 0; t < NTILES; t++) {
        const int m0 = t * 128;
        __syncthreads();   // previous tile's reads done
        load_tile(sb + OFF_KHI, d_ph_hi + (size_t)(b * NN + m0) * CI, CI);
        load_tile(sb + OFF_KLO, d_ph_lo + (size_t)(b * NN + m0) * CI, CI);
        load_tile(sb + OFF_GHI, d_g_hi + (size_t)b * CI * NN + m0, NN);
        load_tile(sb + OFF_GLO, d_g_lo + (size_t)b * CI * NN + m0, NN);
        __syncthreads();

        // ---- S = Qh*Kh^T + Qh*Kl^T + Ql*Kh^T ----
        float s[16][4];
#pragma unroll
        for (int nf = 0; nf < 16; nf++)
#pragma unroll
            for (int j = 0; j < 4; j++) s[nf][j] = 0.0f;

#pragma unroll 1
        for (int kk = 0; kk < 8; kk++) {
            uint32_t qh[4], ql[4];
            ldsm4(qh[0], qh[1], qh[2], qh[3], sw_addr(sb + OFF_QHI, arow, kk * 2 + fhalf));
            ldsm4(ql[0], ql[1], ql[2], ql[3], sw_addr(sb + OFF_QLO, arow, kk * 2 + fhalf));
#pragma unroll
            for (int np = 0; np < 8; np++) {
                uint32_t kh[4], kl[4];
                ldsm4(kh[0], kh[1], kh[2], kh[3], sw_addr(sb + OFF_KHI, np * 16 + frow, kk * 2 + fhalf));
                ldsm4(kl[0], kl[1], kl[2], kl[3], sw_addr(sb + OFF_KLO, np * 16 + frow, kk * 2 + fhalf));
                mma16816(s[2 * np],     qh[0], qh[1], qh[2], qh[3], kh[0], kh[2]);
                mma16816(s[2 * np + 1], qh[0], qh[1], qh[2], qh[3], kh[1], kh[3]);
                mma16816(s[2 * np],     qh[0], qh[1], qh[2], qh[3], kl[0], kl[2]);
                mma16816(s[2 * np + 1], qh[0], qh[1], qh[2], qh[3], kl[1], kl[3]);
                mma16816(s[2 * np],     ql[0], ql[1], ql[2], ql[3], kh[0], kh[2]);
                mma16816(s[2 * np + 1], ql[0], ql[1], ql[2], ql[3], kh[1], kh[3]);
            }
        }

        // ---- online softmax (rows: lane/4 and lane/4+8 within warp's 16) ----
        float tm0 = -INFINITY, tm1 = -INFINITY;
#pragma unroll
        for (int nf = 0; nf < 16; nf++) {
            tm0 = fmaxf(tm0, fmaxf(s[nf][0], s[nf][1]));
            tm1 = fmaxf(tm1, fmaxf(s[nf][2], s[nf][3]));
        }
        tm0 = fmaxf(tm0, __shfl_xor_sync(0xffffffffu, tm0, 1));
        tm0 = fmaxf(tm0, __shfl_xor_sync(0xffffffffu, tm0, 2));
        tm1 = fmaxf(tm1, __shfl_xor_sync(0xffffffffu, tm1, 1));
        tm1 = fmaxf(tm1, __shfl_xor_sync(0xffffffffu, tm1, 2));
        float mn0 = fmaxf(mr0, tm0), mn1 = fmaxf(mr1, tm1);
        float c0 = __expf(mr0 - mn0), c1 = __expf(mr1 - mn1);
        mr0 = mn0; mr1 = mn1;

        uint32_t ph[16][2];
        float rs0 = 0.0f, rs1 = 0.0f;
#pragma unroll
        for (int nf = 0; nf < 16; nf++) {
            float p0 = __expf(s[nf][0] - mn0);
            float p1 = __expf(s[nf][1] - mn0);
            float p2 = __expf(s[nf][2] - mn1);
            float p3 = __expf(s[nf][3] - mn1);
            rs0 += p0 + p1; rs1 += p2 + p3;
            __half2 h01 = __floats2half2_rn(p0, p1);
            __half2 h23 = __floats2half2_rn(p2, p3);
            ph[nf][0] = *(uint32_t*)&h01;
            ph[nf][1] = *(uint32_t*)&h23;
        }
        rs0 += __shfl_xor_sync(0xffffffffu, rs0, 1);
        rs0 += __shfl_xor_sync(0xffffffffu, rs0, 2);
        rs1 += __shfl_xor_sync(0xffffffffu, rs1, 1);
        rs1 += __shfl_xor_sync(0xffffffffu, rs1, 2);
        lr0 = lr0 * c0 + rs0;
        lr1 = lr1 * c1 + rs1;
#pragma unroll
        for (int nf = 0; nf < 16; nf++) {
            o[nf][0] *= c0; o[nf][1] *= c0; o[nf][2] *= c1; o[nf][3] *= c1;
        }

        // ---- O += P * (Ghi + Glo)^T ----
#pragma unroll 1
        for (int kk = 0; kk < 8; kk++) {
            uint32_t a0 = ph[2 * kk][0], a1 = ph[2 * kk][1];
            uint32_t a2 = ph[2 * kk + 1][0], a3 = ph[2 * kk + 1][1];
#pragma unroll
            for (int np = 0; np < 8; np++) {
                uint32_t gh[4], gl[4];
                ldsm4(gh[0], gh[1], gh[2], gh[3], sw_addr(sb + OFF_GHI, np * 16 + frow, kk * 2 + fhalf));
                ldsm4(gl[0], gl[1], gl[2], gl[3], sw_addr(sb + OFF_GLO, np * 16 + frow, kk * 2 + fhalf));
                mma16816(o[2 * np],     a0, a1, a2, a3, gh[0], gh[2]);
                mma16816(o[2 * np + 1], a0, a1, a2, a3, gh[1], gh[3]);
                mma16816(o[2 * np],     a0, a1, a2, a3, gl[0], gl[2]);
                mma16816(o[2 * np + 1], a0, a1, a2, a3, gl[1], gl[3]);
            }
        }
    }

    // ---- epilogue: y = O / l, bounce through smem for coalesced writes ----
    __syncthreads();
    float* epi = (float*)(smem + OFF_EPI);
    const float inv0 = 1.0f / lr0, inv1 = 1.0f / lr1;
    const int q0 = w * 16 + (lane >> 2);
#pragma unroll
    for (int nf = 0; nf < 16; nf++) {
        int c = nf * 8 + (lane & 3) * 2;
        epi[c * 129 + q0]           = o[nf][0] * inv0;
        epi[(c + 1) * 129 + q0]     = o[nf][1] * inv0;
        epi[c * 129 + q0 + 8]       = o[nf][2] * inv1;
        epi[(c + 1) * 129 + q0 + 8] = o[nf][3] * inv1;
    }
    __syncthreads();
#pragma unroll 1
    for (int i = 0; i < 64; i++) {
        int idx = i * 256 + tid;
        int q = idx & 127, c = idx >> 7;
        d_y[(size_t)(b * CI + c) * NN + n0 + q] = epi[c * 129 + q];
    }
}

// ---------------- Kernel 4: W GEMM + bias + residual ----------------
__global__ __launch_bounds__(256) void wgemm_kernel(
    const float* __restrict__ x,
    const float* __restrict__ Ww, const float* __restrict__ Wb)
{
    __shared__ float As[16 * 64];
    __shared__ float Bs[16 * 64];
    const int t = threadIdx.x;
    const int tx = t & 15, ty = t >> 4;
    const int b = blockIdx.z;
    const int o0 = blockIdx.y * 64;
    const int n0 = blockIdx.x * 64;

    float acc[4][4];
#pragma unroll
    for (int i = 0; i < 4; i++)
#pragma unroll
        for (int j = 0; j < 4; j++) acc[i][j] = 0.0f;

    for (int k0 = 0; k0 < CI; k0 += 16) {
#pragma unroll
        for (int pp = 0; pp < 4; pp++) {
            int idx = pp * 256 + t;
            int mm = idx & 63, kk = idx >> 6;
            As[kk * 64 + mm] = Ww[(o0 + mm) * CI + k0 + kk];
        }
#pragma unroll
        for (int pp = 0; pp < 4; pp++) {
            int idx = pp * 256 + t;
            int nn = idx & 63, kk = idx >> 6;
            Bs[kk * 64 + nn] = d_y[(b * CI + k0 + kk) * NN + n0 + nn];
        }
        __syncthreads();
#pragma unroll
        for (int kk = 0; kk < 16; kk++) {
            float4 a4 = *(const float4*)&As[kk * 64 + ty * 4];
            float4 b4 = *(const float4*)&Bs[kk * 64 + tx * 4];
            float av[4] = {a4.x, a4.y, a4.z, a4.w};
            float bv[4] = {b4.x, b4.y, b4.z, b4.w};
#pragma unroll
            for (int i = 0; i < 4; i++)
#pragma unroll
                for (int j = 0; j < 4; j++)
                    acc[i][j] = fmaf(av[i], bv[j], acc[i][j]);
        }
        __syncthreads();
    }
#pragma unroll
    for (int i = 0; i < 4; i++) {
        int o = o0 + ty * 4 + i;
        float bias = Wb[o];
        float4 xr = *(const float4*)&x[(b * COUT + o) * NN + n0 + tx * 4];
        float4 zo;
        zo.x = acc[i][0] + bias + xr.x;
        zo.y = acc[i][1] + bias + xr.y;
        zo.z = acc[i][2] + bias + xr.z;
        zo.w = acc[i][3] + bias + xr.w;
        *(float4*)&d_z[o * (BB * NN) + b * NN + n0 + tx * 4] = zo;
    }
}

// ---------------- Kernel 5: BN stats for z ----------------
__global__ __launch_bounds__(256) void bn_stats_z_kernel(
    const float* __restrict__ bn_gamma, const float* __restrict__ bn_beta)
{
    __shared__ double ssum[256];
    __shared__ double ssq[256];
    const int ch = blockIdx.x;
    const int t = threadIdx.x;
    const float* base = d_z + ch * (BB * NN);
    double s = 0.0, q = 0.0;
    for (int i = t; i < BB * NN; i += 256) {
        float v = base[i];
        s += (double)v;
        q += (double)v * (double)v;
    }
    ssum[t] = s; ssq[t] = q;
    __syncthreads();
    for (int off = 128; off > 0; off >>= 1) {
        if (t < off) { ssum[t] += ssum[t + off]; ssq[t] += ssq[t + off]; }
        __syncthreads();
    }
    if (t == 0) {
        double mean = ssum[0] / (double)(BB * NN);
        double var = ssq[0] / (double)(BB * NN) - mean * mean;
        float sc = bn_gamma[ch] / sqrtf((float)var + BN_EPS);
        d_zscale[ch] = sc;
        d_zshift[ch] = bn_beta[ch] - (float)mean * sc;
    }
}

// ---------------- Kernel 6: final normalize ----------------
__global__ __launch_bounds__(256) void finalize_kernel(float* __restrict__ out)
{
    int idx = blockIdx.x * 256 + threadIdx.x;
    int o = idx >> 14;
    int rem = idx & 16383;
    int b = rem >> 12;
    int n = rem & 4095;
    out[(b * COUT + o) * NN + n] = d_z[idx] * d_zscale[o] + d_zshift[o];
}

// ---------------- host launcher ----------------
extern "C" void kernel_launch(void* const* d_in, const int* in_sizes, int n_in,
                              void* d_out, int out_size)
{
    const float* x        = (const float*)d_in[0];
    const float* g_w      = (const float*)d_in[1];
    const float* g_b      = (const float*)d_in[2];
    const float* g_gamma  = (const float*)d_in[3];
    const float* g_beta   = (const float*)d_in[4];
    const float* th_w     = (const float*)d_in[5];
    const float* th_b     = (const float*)d_in[6];
    const float* th_gamma = (const float*)d_in[7];
    const float* th_beta  = (const float*)d_in[8];
    const float* ph_w     = (const float*)d_in[9];
    const float* ph_b     = (const float*)d_in[10];
    const float* ph_gamma = (const float*)d_in[11];
    const float* ph_beta  = (const float*)d_in[12];
    const float* W_w      = (const float*)d_in[13];
    const float* W_b      = (const float*)d_in[14];
    const float* bn_gamma = (const float*)d_in[15];
    const float* bn_beta  = (const float*)d_in[16];
    float* out = (float*)d_out;

    cudaFuncSetAttribute(attn_mma_kernel, cudaFuncAttributeMaxDynamicSharedMemorySize, ATTN_SMEM_BYTES);

    proj_gemm_kernel<<<dim3(NN / 64, CP / 64, BB), 256>>>(x, g_w, g_b, th_w, th_b, ph_w, ph_b);
    bn_stats_proj_kernel<<<CP, 256>>>(g_gamma, g_beta, th_gamma, th_beta, ph_gamma, ph_beta);
    prep_qk_kernel<<<dim3(NN / 32, CI / 32, BB * 2), 256>>>();
    prep_g_kernel<<<(BB * CI * NN / 4) / 256, 256>>>();
    attn_mma_kernel<<<dim3(NTILES, BB), 256, ATTN_SMEM_BYTES>>>();
    wgemm_kernel<<<dim3(NN / 64, COUT / 64, BB), 256>>>(x, W_w, W_b);
    bn_stats_z_kernel<<<COUT, 256>>>(bn_gamma, bn_beta);
    finalize_kernel<<<(COUT * BB * NN) / 256, 256>>>(out);
}

// round 5
// speedup vs baseline: 3.7336x; 1.3650x over previous
#include <cuda_runtime.h>
#include <cuda_fp16.h>
#include <math.h>
#include <stdint.h>

// Problem constants
#define BB 4
#define CIN 256
#define CI 128
#define NN 4096          // H*W = 64*64
#define CP 384           // 3*CI projection channels
#define COUT 256
#define BN_EPS 1e-5f
#define NTILES 32        // NN / 128 key tiles

// Scratch (static device globals; allocation APIs are forbidden)
__device__ float d_proj[CP * BB * NN];     // [m][b][n], m: 0..127=g, 128..255=theta, 256..383=phi
__device__ float d_pscale[CP];
__device__ float d_pshift[CP];
__device__ float d_z[COUT * BB * NN];      // [o][b][n]
__device__ float d_zscale[COUT];
__device__ float d_zshift[COUT];

// fp16 hi/lo split operands
__device__ __half d_xt_hi[BB * NN * CIN];  // x^T      [b][n][c]
__device__ __half d_xt_lo[BB * NN * CIN];
__device__ __half d_th_hi[BB * NN * CI];   // theta^T  [b][n][c]
__device__ __half d_th_lo[BB * NN * CI];
__device__ __half d_ph_hi[BB * NN * CI];   // phi^T    [b][n][c]
__device__ __half d_ph_lo[BB * NN * CI];
__device__ __half d_g_hi[BB * CI * NN];    // g        [b][c][n]
__device__ __half d_g_lo[BB * CI * NN];
__device__ __half d_y_hi[BB * NN * CI];    // y^T      [b][n][c] (attention output)
__device__ __half d_y_lo[BB * NN * CI];

// ======================= helpers =======================
__device__ __forceinline__ uint32_t smem_u32(const void* p) {
    uint32_t a;
    asm("{ .reg .u64 t; cvta.to.shared.u64 t, %1; cvt.u32.u64 %0, t; }" : "=r"(a) : "l"(p));
    return a;
}

__device__ __forceinline__ void ldsm4(uint32_t& r0, uint32_t& r1, uint32_t& r2, uint32_t& r3,
                                      uint32_t addr) {
    asm volatile("ldmatrix.sync.aligned.m8n8.x4.shared.b16 {%0,%1,%2,%3}, [%4];"
                 : "=r"(r0), "=r"(r1), "=r"(r2), "=r"(r3) : "r"(addr));
}

__device__ __forceinline__ void mma16816(float* d, uint32_t a0, uint32_t a1, uint32_t a2, uint32_t a3,
                                         uint32_t b0, uint32_t b1) {
    asm volatile(
        "mma.sync.aligned.m16n8k16.row.col.f32.f16.f16.f32 "
        "{%0,%1,%2,%3}, {%4,%5,%6,%7}, {%8,%9}, {%0,%1,%2,%3};"
        : "+f"(d[0]), "+f"(d[1]), "+f"(d[2]), "+f"(d[3])
        : "r"(a0), "r"(a1), "r"(a2), "r"(a3), "r"(b0), "r"(b1));
}

// swizzled tile address: 128 rows x 128 halfs (256B rows), 16B chunks XOR'd with row&7
__device__ __forceinline__ uint32_t sw_addr(uint32_t base, int row, int chunk) {
    return base + (uint32_t)row * 256u + (uint32_t)((chunk ^ (row & 7)) << 4);
}

__device__ __forceinline__ uint32_t packh2(__half a, __half b) {
    __half2 h = __halves2half2(a, b);
    return *(uint32_t*)&h;
}

// cooperative load of a 128x128 half tile into swizzled smem (256 threads)
__device__ __forceinline__ void load_tile(uint32_t dst, const __half* __restrict__ src,
                                          int row_stride) {
    const int t = threadIdx.x;
#pragma unroll
    for (int i = 0; i < 8; i++) {
        int cid = i * 256 + t;
        int row = cid >> 4, c = cid & 15;
        uint4 v = *(const uint4*)(src + (size_t)row * row_stride + c * 8);
        uint32_t a = sw_addr(dst, row, c);
        asm volatile("st.shared.v4.b32 [%0], {%1, %2, %3, %4};"
                     :: "r"(a), "r"(v.x), "r"(v.y), "r"(v.z), "r"(v.w));
    }
}

// cooperative split-load of a 128x128 fp32 block into swizzled hi/lo fp16 tiles
__device__ __forceinline__ void split_tile(uint32_t dhi, uint32_t dlo,
                                           const float* __restrict__ src, int row_stride) {
    const int t = threadIdx.x;
#pragma unroll
    for (int i = 0; i < 8; i++) {
        int cid = i * 256 + t;
        int row = cid >> 4, c = cid & 15;
        const float* p = src + (size_t)row * row_stride + c * 8;
        float4 v0 = *(const float4*)p;
        float4 v1 = *(const float4*)(p + 4);
        float e[8] = {v0.x, v0.y, v0.z, v0.w, v1.x, v1.y, v1.z, v1.w};
        __half h[8], l[8];
#pragma unroll
        for (int j = 0; j < 8; j++) {
            h[j] = __float2half_rn(e[j]);
            l[j] = __float2half_rn(e[j] - __half2float(h[j]));
        }
        uint32_t hw0 = packh2(h[0], h[1]), hw1 = packh2(h[2], h[3]);
        uint32_t hw2 = packh2(h[4], h[5]), hw3 = packh2(h[6], h[7]);
        uint32_t lw0 = packh2(l[0], l[1]), lw1 = packh2(l[2], l[3]);
        uint32_t lw2 = packh2(l[4], l[5]), lw3 = packh2(l[6], l[7]);
        asm volatile("st.shared.v4.b32 [%0], {%1, %2, %3, %4};"
                     :: "r"(sw_addr(dhi, row, c)), "r"(hw0), "r"(hw1), "r"(hw2), "r"(hw3));
        asm volatile("st.shared.v4.b32 [%0], {%1, %2, %3, %4};"
                     :: "r"(sw_addr(dlo, row, c)), "r"(lw0), "r"(lw1), "r"(lw2), "r"(lw3));
    }
}

// ---------------- Kernel 0: transpose+split x -> [b][n][c] fp16 hi/lo ----------------
__global__ __launch_bounds__(256) void prep_xt_kernel(const float* __restrict__ x)
{
    __shared__ float tile[32][33];
    const int t = threadIdx.x;
    const int tx = t & 31, ty = t >> 5;
    const int b = blockIdx.z;
    const int c0 = blockIdx.y * 32;
    const int n0 = blockIdx.x * 32;
#pragma unroll
    for (int i = 0; i < 4; i++) {
        int c = c0 + ty + i * 8;
        tile[ty + i * 8][tx] = x[(size_t)(b * CIN + c) * NN + n0 + tx];
    }
    __syncthreads();
#pragma unroll
    for (int i = 0; i < 4; i++) {
        int n = n0 + ty + i * 8;
        float v = tile[tx][ty + i * 8];
        __half h = __float2half_rn(v);
        __half l = __float2half_rn(v - __half2float(h));
        size_t idx = (size_t)(b * NN + n) * CIN + c0 + tx;
        d_xt_hi[idx] = h;
        d_xt_lo[idx] = l;
    }
}

// ---------------- Kernel 1: tensor-core projection GEMM ----------------
// proj[m][b][n] = sum_k Wsel[m][k] * x[b][k][n] + bias.  Tile 128m x 128n, k=256 (2 chunks).
#define TG_A_HI 0
#define TG_A_LO 32768
#define TG_B_HI 65536
#define TG_B_LO 98304
#define TG_SMEM_BYTES 131072

__global__ __launch_bounds__(256, 1) void proj_tc_kernel(
    const float* __restrict__ gw, const float* __restrict__ gb,
    const float* __restrict__ thw, const float* __restrict__ thb,
    const float* __restrict__ phw, const float* __restrict__ phb)
{
    extern __shared__ char smem[];
    const uint32_t sb = smem_u32(smem);
    const int t = threadIdx.x;
    const int lane = t & 31, w = t >> 5;
    const int b = blockIdx.z;
    const int m0 = blockIdx.y * 128;     // 0 / 128 / 256
    const int n0 = blockIdx.x * 128;

    const float* wsrc;
    const float* bsrc;
    if (m0 == 0)        { wsrc = gw;  bsrc = gb;  }
    else if (m0 == 128) { wsrc = thw; bsrc = thb; }
    else                { wsrc = phw; bsrc = phb; }

    const int frow = lane & 15, fhalf = lane >> 4;
    const int arow = w * 16 + frow;

    float acc[16][4];
#pragma unroll
    for (int nf = 0; nf < 16; nf++)
#pragma unroll
        for (int j = 0; j < 4; j++) acc[nf][j] = 0.0f;

#pragma unroll 1
    for (int k0 = 0; k0 < CIN; k0 += 128) {
        __syncthreads();
        split_tile(sb + TG_A_HI, sb + TG_A_LO, wsrc + k0, CIN);
        load_tile(sb + TG_B_HI, d_xt_hi + (size_t)(b * NN + n0) * CIN + k0, CIN);
        load_tile(sb + TG_B_LO, d_xt_lo + (size_t)(b * NN + n0) * CIN + k0, CIN);
        __syncthreads();

#pragma unroll 1
        for (int kk = 0; kk < 8; kk++) {
            uint32_t ah[4], al[4];
            ldsm4(ah[0], ah[1], ah[2], ah[3], sw_addr(sb + TG_A_HI, arow, kk * 2 + fhalf));
            ldsm4(al[0], al[1], al[2], al[3], sw_addr(sb + TG_A_LO, arow, kk * 2 + fhalf));
#pragma unroll
            for (int np = 0; np < 8; np++) {
                uint32_t bh[4], bl[4];
                ldsm4(bh[0], bh[1], bh[2], bh[3], sw_addr(sb + TG_B_HI, np * 16 + frow, kk * 2 + fhalf));
                ldsm4(bl[0], bl[1], bl[2], bl[3], sw_addr(sb + TG_B_LO, np * 16 + frow, kk * 2 + fhalf));
                mma16816(acc[2 * np],     ah[0], ah[1], ah[2], ah[3], bh[0], bh[2]);
                mma16816(acc[2 * np + 1], ah[0], ah[1], ah[2], ah[3], bh[1], bh[3]);
                mma16816(acc[2 * np],     ah[0], ah[1], ah[2], ah[3], bl[0], bl[2]);
                mma16816(acc[2 * np + 1], ah[0], ah[1], ah[2], ah[3], bl[1], bl[3]);
                mma16816(acc[2 * np],     al[0], al[1], al[2], al[3], bh[0], bh[2]);
                mma16816(acc[2 * np + 1], al[0], al[1], al[2], al[3], bh[1], bh[3]);
            }
        }
    }

    // epilogue: bias add + direct stores (float2 per frag row)
    const int r0 = w * 16 + (lane >> 2);
    const float bias0 = bsrc[r0];
    const float bias1 = bsrc[r0 + 8];
    float* out0 = d_proj + (size_t)(m0 + r0) * (BB * NN) + (size_t)b * NN + n0;
    float* out1 = d_proj + (size_t)(m0 + r0 + 8) * (BB * NN) + (size_t)b * NN + n0;
#pragma unroll
    for (int nf = 0; nf < 16; nf++) {
        int n = nf * 8 + (lane & 3) * 2;
        *(float2*)(out0 + n) = make_float2(acc[nf][0] + bias0, acc[nf][1] + bias0);
        *(float2*)(out1 + n) = make_float2(acc[nf][2] + bias1, acc[nf][3] + bias1);
    }
}

// ---------------- Kernel 2: BN stats for projections ----------------
__global__ __launch_bounds__(256) void bn_stats_proj_kernel(
    const float* __restrict__ g_gamma, const float* __restrict__ g_beta,
    const float* __restrict__ th_gamma, const float* __restrict__ th_beta,
    const float* __restrict__ ph_gamma, const float* __restrict__ ph_beta)
{
    __shared__ double ssum[256];
    __shared__ double ssq[256];
    const int ch = blockIdx.x;
    const int t = threadIdx.x;
    const float* base = d_proj + ch * (BB * NN);
    double s = 0.0, q = 0.0;
    for (int i = t; i < BB * NN; i += 256) {
        float v = base[i];
        s += (double)v;
        q += (double)v * (double)v;
    }
    ssum[t] = s; ssq[t] = q;
    __syncthreads();
    for (int off = 128; off > 0; off >>= 1) {
        if (t < off) { ssum[t] += ssum[t + off]; ssq[t] += ssq[t + off]; }
        __syncthreads();
    }
    if (t == 0) {
        double mean = ssum[0] / (double)(BB * NN);
        double var = ssq[0] / (double)(BB * NN) - mean * mean;
        float gamma, beta;
        if (ch < 128)      { gamma = g_gamma[ch];        beta = g_beta[ch]; }
        else if (ch < 256) { gamma = th_gamma[ch - 128]; beta = th_beta[ch - 128]; }
        else               { gamma = ph_gamma[ch - 256]; beta = ph_beta[ch - 256]; }
        float sc = gamma / sqrtf((float)var + BN_EPS);
        d_pscale[ch] = sc;
        d_pshift[ch] = beta - (float)mean * sc;
    }
}

// ---------------- Kernel 2b: prep theta/phi -> fp16 hi/lo, transposed to [b][n][c] ----------------
__global__ __launch_bounds__(256) void prep_qk_kernel()
{
    __shared__ float tile[32][33];
    const int t = threadIdx.x;
    const int tx = t & 31, ty = t >> 5;
    const int sel = blockIdx.z >> 2;      // 0: theta, 1: phi
    const int b = blockIdx.z & 3;
    const int c0 = blockIdx.y * 32;
    const int n0 = blockIdx.x * 32;
    const int chbase = 128 + sel * 128;
#pragma unroll
    for (int i = 0; i < 4; i++) {
        int c = c0 + ty + i * 8;
        float v = d_proj[(size_t)(chbase + c) * (BB * NN) + (size_t)b * NN + n0 + tx];
        tile[ty + i * 8][tx] = v * d_pscale[chbase + c] + d_pshift[chbase + c];
    }
    __syncthreads();
    __half* hi = sel ? d_ph_hi : d_th_hi;
    __half* lo = sel ? d_ph_lo : d_th_lo;
#pragma unroll
    for (int i = 0; i < 4; i++) {
        int n = n0 + ty + i * 8;
        float v = tile[tx][ty + i * 8];
        __half h = __float2half_rn(v);
        __half l = __float2half_rn(v - __half2float(h));
        size_t idx = (size_t)(b * NN + n) * CI + c0 + tx;
        hi[idx] = h;
        lo[idx] = l;
    }
}

// ---------------- Kernel 2c: prep g -> fp16 hi/lo, [b][c][n] ----------------
__global__ __launch_bounds__(256) void prep_g_kernel()
{
    int i = blockIdx.x * 256 + threadIdx.x;  // over BB*CI*NN/4
    int n4 = i & (NN / 4 - 1);
    int rest = i / (NN / 4);
    int c = rest & (CI - 1);
    int b = rest >> 7;
    float4 v = *(const float4*)&d_proj[(size_t)c * (BB * NN) + (size_t)b * NN + n4 * 4];
    float sc = d_pscale[c], sh = d_pshift[c];
    float a0 = v.x * sc + sh, a1 = v.y * sc + sh, a2 = v.z * sc + sh, a3 = v.w * sc + sh;
    __half h0 = __float2half_rn(a0), h1 = __float2half_rn(a1);
    __half h2 = __float2half_rn(a2), h3 = __float2half_rn(a3);
    __half l0 = __float2half_rn(a0 - __half2float(h0));
    __half l1 = __float2half_rn(a1 - __half2float(h1));
    __half l2 = __float2half_rn(a2 - __half2float(h2));
    __half l3 = __float2half_rn(a3 - __half2float(h3));
    size_t base = (size_t)(b * CI + c) * NN + n4 * 4;
    *(__half2*)&d_g_hi[base]     = __halves2half2(h0, h1);
    *(__half2*)&d_g_hi[base + 2] = __halves2half2(h2, h3);
    *(__half2*)&d_g_lo[base]     = __halves2half2(l0, l1);
    *(__half2*)&d_g_lo[base + 2] = __halves2half2(l2, l3);
}

// ---------------- Kernel 3: mma.sync flash attention (fp16 hi/lo split) ----------------
#define OFF_QHI 0
#define OFF_QLO 32768
#define OFF_KHI 65536
#define OFF_KLO 98304
#define OFF_GHI 131072
#define OFF_GLO 163840
#define ATTN_SMEM_BYTES 196608

__global__ __launch_bounds__(256, 1) void attn_mma_kernel()
{
    extern __shared__ char smem[];
    const uint32_t sb = smem_u32(smem);
    const int tid = threadIdx.x;
    const int lane = tid & 31;
    const int w = tid >> 5;
    const int b = blockIdx.y;
    const int n0 = blockIdx.x * 128;

    load_tile(sb + OFF_QHI, d_th_hi + (size_t)(b * NN + n0) * CI, CI);
    load_tile(sb + OFF_QLO, d_th_lo + (size_t)(b * NN + n0) * CI, CI);

    const int frow = lane & 15;
    const int fhalf = lane >> 4;
    const int arow = w * 16 + frow;

    float o[16][4];
#pragma unroll
    for (int nf = 0; nf < 16; nf++)
#pragma unroll
        for (int j = 0; j < 4; j++) o[nf][j] = 0.0f;
    float mr0 = -INFINITY, mr1 = -INFINITY, lr0 = 0.0f, lr1 = 0.0f;

    for (int t = 0; t < NTILES; t++) {
        const int m0 = t * 128;
        __syncthreads();
        load_tile(sb + OFF_KHI, d_ph_hi + (size_t)(b * NN + m0) * CI, CI);
        load_tile(sb + OFF_KLO, d_ph_lo + (size_t)(b * NN + m0) * CI, CI);
        load_tile(sb + OFF_GHI, d_g_hi + (size_t)b * CI * NN + m0, NN);
        load_tile(sb + OFF_GLO, d_g_lo + (size_t)b * CI * NN + m0, NN);
        __syncthreads();

        float s[16][4];
#pragma unroll
        for (int nf = 0; nf < 16; nf++)
#pragma unroll
            for (int j = 0; j < 4; j++) s[nf][j] = 0.0f;

#pragma unroll 1
        for (int kk = 0; kk < 8; kk++) {
            uint32_t qh[4], ql[4];
            ldsm4(qh[0], qh[1], qh[2], qh[3], sw_addr(sb + OFF_QHI, arow, kk * 2 + fhalf));
            ldsm4(ql[0], ql[1], ql[2], ql[3], sw_addr(sb + OFF_QLO, arow, kk * 2 + fhalf));
#pragma unroll
            for (int np = 0; np < 8; np++) {
                uint32_t kh[4], kl[4];
                ldsm4(kh[0], kh[1], kh[2], kh[3], sw_addr(sb + OFF_KHI, np * 16 + frow, kk * 2 + fhalf));
                ldsm4(kl[0], kl[1], kl[2], kl[3], sw_addr(sb + OFF_KLO, np * 16 + frow, kk * 2 + fhalf));
                mma16816(s[2 * np],     qh[0], qh[1], qh[2], qh[3], kh[0], kh[2]);
                mma16816(s[2 * np + 1], qh[0], qh[1], qh[2], qh[3], kh[1], kh[3]);
                mma16816(s[2 * np],     qh[0], qh[1], qh[2], qh[3], kl[0], kl[2]);
                mma16816(s[2 * np + 1], qh[0], qh[1], qh[2], qh[3], kl[1], kl[3]);
                mma16816(s[2 * np],     ql[0], ql[1], ql[2], ql[3], kh[0], kh[2]);
                mma16816(s[2 * np + 1], ql[0], ql[1], ql[2], ql[3], kh[1], kh[3]);
            }
        }

        float tm0 = -INFINITY, tm1 = -INFINITY;
#pragma unroll
        for (int nf = 0; nf < 16; nf++) {
            tm0 = fmaxf(tm0, fmaxf(s[nf][0], s[nf][1]));
            tm1 = fmaxf(tm1, fmaxf(s[nf][2], s[nf][3]));
        }
        tm0 = fmaxf(tm0, __shfl_xor_sync(0xffffffffu, tm0, 1));
        tm0 = fmaxf(tm0, __shfl_xor_sync(0xffffffffu, tm0, 2));
        tm1 = fmaxf(tm1, __shfl_xor_sync(0xffffffffu, tm1, 1));
        tm1 = fmaxf(tm1, __shfl_xor_sync(0xffffffffu, tm1, 2));
        float mn0 = fmaxf(mr0, tm0), mn1 = fmaxf(mr1, tm1);
        float c0 = __expf(mr0 - mn0), c1 = __expf(mr1 - mn1);
        mr0 = mn0; mr1 = mn1;

        uint32_t ph[16][2];
        float rs0 = 0.0f, rs1 = 0.0f;
#pragma unroll
        for (int nf = 0; nf < 16; nf++) {
            float p0 = __expf(s[nf][0] - mn0);
            float p1 = __expf(s[nf][1] - mn0);
            float p2 = __expf(s[nf][2] - mn1);
            float p3 = __expf(s[nf][3] - mn1);
            rs0 += p0 + p1; rs1 += p2 + p3;
            __half2 h01 = __floats2half2_rn(p0, p1);
            __half2 h23 = __floats2half2_rn(p2, p3);
            ph[nf][0] = *(uint32_t*)&h01;
            ph[nf][1] = *(uint32_t*)&h23;
        }
        rs0 += __shfl_xor_sync(0xffffffffu, rs0, 1);
        rs0 += __shfl_xor_sync(0xffffffffu, rs0, 2);
        rs1 += __shfl_xor_sync(0xffffffffu, rs1, 1);
        rs1 += __shfl_xor_sync(0xffffffffu, rs1, 2);
        lr0 = lr0 * c0 + rs0;
        lr1 = lr1 * c1 + rs1;
#pragma unroll
        for (int nf = 0; nf < 16; nf++) {
            o[nf][0] *= c0; o[nf][1] *= c0; o[nf][2] *= c1; o[nf][3] *= c1;
        }

#pragma unroll 1
        for (int kk = 0; kk < 8; kk++) {
            uint32_t a0 = ph[2 * kk][0], a1 = ph[2 * kk][1];
            uint32_t a2 = ph[2 * kk + 1][0], a3 = ph[2 * kk + 1][1];
#pragma unroll
            for (int np = 0; np < 8; np++) {
                uint32_t gh[4], gl[4];
                ldsm4(gh[0], gh[1], gh[2], gh[3], sw_addr(sb + OFF_GHI, np * 16 + frow, kk * 2 + fhalf));
                ldsm4(gl[0], gl[1], gl[2], gl[3], sw_addr(sb + OFF_GLO, np * 16 + frow, kk * 2 + fhalf));
                mma16816(o[2 * np],     a0, a1, a2, a3, gh[0], gh[2]);
                mma16816(o[2 * np + 1], a0, a1, a2, a3, gh[1], gh[3]);
                mma16816(o[2 * np],     a0, a1, a2, a3, gl[0], gl[2]);
                mma16816(o[2 * np + 1], a0, a1, a2, a3, gl[1], gl[3]);
            }
        }
    }

    // epilogue: y = O / l, split hi/lo, store directly as [b][n][c] fp16 (half2 per frag)
    const float inv0 = 1.0f / lr0, inv1 = 1.0f / lr1;
    const int q0 = n0 + w * 16 + (lane >> 2);
    __half* yh0 = d_y_hi + (size_t)(b * NN + q0) * CI;
    __half* yl0 = d_y_lo + (size_t)(b * NN + q0) * CI;
    __half* yh1 = d_y_hi + (size_t)(b * NN + q0 + 8) * CI;
    __half* yl1 = d_y_lo + (size_t)(b * NN + q0 + 8) * CI;
#pragma unroll
    for (int nf = 0; nf < 16; nf++) {
        int c = nf * 8 + (lane & 3) * 2;
        float v0 = o[nf][0] * inv0, v1 = o[nf][1] * inv0;
        float v2 = o[nf][2] * inv1, v3 = o[nf][3] * inv1;
        __half h0 = __float2half_rn(v0), h1 = __float2half_rn(v1);
        __half h2 = __float2half_rn(v2), h3 = __float2half_rn(v3);
        *(__half2*)(yh0 + c) = __halves2half2(h0, h1);
        *(__half2*)(yl0 + c) = __halves2half2(__float2half_rn(v0 - __half2float(h0)),
                                              __float2half_rn(v1 - __half2float(h1)));
        *(__half2*)(yh1 + c) = __halves2half2(h2, h3);
        *(__half2*)(yl1 + c) = __halves2half2(__float2half_rn(v2 - __half2float(h2)),
                                              __float2half_rn(v3 - __half2float(h3)));
    }
}

// ---------------- Kernel 4: tensor-core W GEMM + bias + residual ----------------
// z[o][b][n] = sum_c Ww[o][c]*y[b][n][c] + Wb[o] + x[b][o][n].  k=128, single chunk.
__global__ __launch_bounds__(256, 1) void wgemm_tc_kernel(
    const float* __restrict__ x,
    const float* __restrict__ Ww, const float* __restrict__ Wb)
{
    extern __shared__ char smem[];
    const uint32_t sb = smem_u32(smem);
    const int t = threadIdx.x;
    const int lane = t & 31, w = t >> 5;
    const int b = blockIdx.z;
    const int o0 = blockIdx.y * 128;
    const int n0 = blockIdx.x * 128;

    const int frow = lane & 15, fhalf = lane >> 4;
    const int arow = w * 16 + frow;

    split_tile(sb + TG_A_HI, sb + TG_A_LO, Ww + (size_t)o0 * CI, CI);
    load_tile(sb + TG_B_HI, d_y_hi + (size_t)(b * NN + n0) * CI, CI);
    load_tile(sb + TG_B_LO, d_y_lo + (size_t)(b * NN + n0) * CI, CI);
    __syncthreads();

    float acc[16][4];
#pragma unroll
    for (int nf = 0; nf < 16; nf++)
#pragma unroll
        for (int j = 0; j < 4; j++) acc[nf][j] = 0.0f;

#pragma unroll 1
    for (int kk = 0; kk < 8; kk++) {
        uint32_t ah[4], al[4];
        ldsm4(ah[0], ah[1], ah[2], ah[3], sw_addr(sb + TG_A_HI, arow, kk * 2 + fhalf));
        ldsm4(al[0], al[1], al[2], al[3], sw_addr(sb + TG_A_LO, arow, kk * 2 + fhalf));
#pragma unroll
        for (int np = 0; np < 8; np++) {
            uint32_t bh[4], bl[4];
            ldsm4(bh[0], bh[1], bh[2], bh[3], sw_addr(sb + TG_B_HI, np * 16 + frow, kk * 2 + fhalf));
            ldsm4(bl[0], bl[1], bl[2], bl[3], sw_addr(sb + TG_B_LO, np * 16 + frow, kk * 2 + fhalf));
            mma16816(acc[2 * np],     ah[0], ah[1], ah[2], ah[3], bh[0], bh[2]);
            mma16816(acc[2 * np + 1], ah[0], ah[1], ah[2], ah[3], bh[1], bh[3]);
            mma16816(acc[2 * np],     ah[0], ah[1], ah[2], ah[3], bl[0], bl[2]);
            mma16816(acc[2 * np + 1], ah[0], ah[1], ah[2], ah[3], bl[1], bl[3]);
            mma16816(acc[2 * np],     al[0], al[1], al[2], al[3], bh[0], bh[2]);
            mma16816(acc[2 * np + 1], al[0], al[1], al[2], al[3], bh[1], bh[3]);
        }
    }

    // epilogue: bias + residual + store
    const int r0 = o0 + w * 16 + (lane >> 2);
    const float bias0 = Wb[r0], bias1 = Wb[r0 + 8];
    const float* xr0 = x + (size_t)(b * COUT + r0) * NN + n0;
    const float* xr1 = x + (size_t)(b * COUT + r0 + 8) * NN + n0;
    float* z0 = d_z + (size_t)r0 * (BB * NN) + (size_t)b * NN + n0;
    float* z1 = d_z + (size_t)(r0 + 8) * (BB * NN) + (size_t)b * NN + n0;
#pragma unroll
    for (int nf = 0; nf < 16; nf++) {
        int n = nf * 8 + (lane & 3) * 2;
        float2 xa = *(const float2*)(xr0 + n);
        float2 xb = *(const float2*)(xr1 + n);
        *(float2*)(z0 + n) = make_float2(acc[nf][0] + bias0 + xa.x, acc[nf][1] + bias0 + xa.y);
        *(float2*)(z1 + n) = make_float2(acc[nf][2] + bias1 + xb.x, acc[nf][3] + bias1 + xb.y);
    }
}

// ---------------- Kernel 5: BN stats for z ----------------
__global__ __launch_bounds__(256) void bn_stats_z_kernel(
    const float* __restrict__ bn_gamma, const float* __restrict__ bn_beta)
{
    __shared__ double ssum[256];
    __shared__ double ssq[256];
    const int ch = blockIdx.x;
    const int t = threadIdx.x;
    const float* base = d_z + ch * (BB * NN);
    double s = 0.0, q = 0.0;
    for (int i = t; i < BB * NN; i += 256) {
        float v = base[i];
        s += (double)v;
        q += (double)v * (double)v;
    }
    ssum[t] = s; ssq[t] = q;
    __syncthreads();
    for (int off = 128; off > 0; off >>= 1) {
        if (t < off) { ssum[t] += ssum[t + off]; ssq[t] += ssq[t + off]; }
        __syncthreads();
    }
    if (t == 0) {
        double mean = ssum[0] / (double)(BB * NN);
        double var = ssq[0] / (double)(BB * NN) - mean * mean;
        float sc = bn_gamma[ch] / sqrtf((float)var + BN_EPS);
        d_zscale[ch] = sc;
        d_zshift[ch] = bn_beta[ch] - (float)mean * sc;
    }
}

// ---------------- Kernel 6: final normalize ----------------
__global__ __launch_bounds__(256) void finalize_kernel(float* __restrict__ out)
{
    int idx = blockIdx.x * 256 + threadIdx.x;
    int o = idx >> 14;
    int rem = idx & 16383;
    int b = rem >> 12;
    int n = rem & 4095;
    out[(b * COUT + o) * NN + n] = d_z[idx] * d_zscale[o] + d_zshift[o];
}

// ---------------- host launcher ----------------
extern "C" void kernel_launch(void* const* d_in, const int* in_sizes, int n_in,
                              void* d_out, int out_size)
{
    const float* x        = (const float*)d_in[0];
    const float* g_w      = (const float*)d_in[1];
    const float* g_b      = (const float*)d_in[2];
    const float* g_gamma  = (const float*)d_in[3];
    const float* g_beta   = (const float*)d_in[4];
    const float* th_w     = (const float*)d_in[5];
    const float* th_b     = (const float*)d_in[6];
    const float* th_gamma = (const float*)d_in[7];
    const float* th_beta  = (const float*)d_in[8];
    const float* ph_w     = (const float*)d_in[9];
    const float* ph_b     = (const float*)d_in[10];
    const float* ph_gamma = (const float*)d_in[11];
    const float* ph_beta  = (const float*)d_in[12];
    const float* W_w      = (const float*)d_in[13];
    const float* W_b      = (const float*)d_in[14];
    const float* bn_gamma = (const float*)d_in[15];
    const float* bn_beta  = (const float*)d_in[16];
    float* out = (float*)d_out;

    cudaFuncSetAttribute(proj_tc_kernel, cudaFuncAttributeMaxDynamicSharedMemorySize, TG_SMEM_BYTES);
    cudaFuncSetAttribute(wgemm_tc_kernel, cudaFuncAttributeMaxDynamicSharedMemorySize, TG_SMEM_BYTES);
    cudaFuncSetAttribute(attn_mma_kernel, cudaFuncAttributeMaxDynamicSharedMemorySize, ATTN_SMEM_BYTES);

    prep_xt_kernel<<<dim3(NN / 32, CIN / 32, BB), 256>>>(x);
    proj_tc_kernel<<<dim3(NN / 128, CP / 128, BB), 256, TG_SMEM_BYTES>>>(
        g_w, g_b, th_w, th_b, ph_w, ph_b);
    bn_stats_proj_kernel<<<CP, 256>>>(g_gamma, g_beta, th_gamma, th_beta, ph_gamma, ph_beta);
    prep_qk_kernel<<<dim3(NN / 32, CI / 32, BB * 2), 256>>>();
    prep_g_kernel<<<(BB * CI * NN / 4) / 256, 256>>>();
    attn_mma_kernel<<<dim3(NTILES, BB), 256, ATTN_SMEM_BYTES>>>();
    wgemm_tc_kernel<<<dim3(NN / 128, COUT / 128, BB), 256, TG_SMEM_BYTES>>>(x, W_w, W_b);
    bn_stats_z_kernel<<<COUT, 256>>>(bn_gamma, bn_beta);
    finalize_kernel<<<(COUT * BB * NN) / 256, 256>>>(out);
}

// round 6
// speedup vs baseline: 4.0990x; 1.0979x over previous
#include <cuda_runtime.h>
#include <cuda_fp16.h>
#include <math.h>
#include <stdint.h>

// Problem constants
#define BB 4
#define CIN 256
#define CI 128
#define NN 4096          // H*W = 64*64
#define CP 384           // 3*CI projection channels
#define COUT 256
#define BN_EPS 1e-5f
#define NTILES 32        // NN / 128 key tiles

// Scratch (static device globals; allocation APIs are forbidden)
__device__ float d_proj[CP * BB * NN];     // [m][b][n], m: 0..127=g, 128..255=theta, 256..383=phi
__device__ float d_pscale[CP];
__device__ float d_pshift[CP];
__device__ float d_z[COUT * BB * NN];      // [o][b][n]
__device__ float d_zscale[COUT];
__device__ float d_zshift[COUT];

// fp16 hi/lo split operands
__device__ __half d_xt_hi[BB * NN * CIN];  // x^T      [b][n][c]
__device__ __half d_xt_lo[BB * NN * CIN];
__device__ __half d_th_hi[BB * NN * CI];   // theta^T  [b][n][c]
__device__ __half d_th_lo[BB * NN * CI];
__device__ __half d_ph_hi[BB * NN * CI];   // phi^T    [b][n][c]
__device__ __half d_ph_lo[BB * NN * CI];
__device__ __half d_g_hi[BB * CI * NN];    // g        [b][c][n]
__device__ __half d_g_lo[BB * CI * NN];    // (kept for layout symmetry; unused by attention now)
__device__ __half d_y_hi[BB * NN * CI];    // y^T      [b][n][c] (attention output)
__device__ __half d_y_lo[BB * NN * CI];

// ======================= helpers =======================
__device__ __forceinline__ uint32_t smem_u32(const void* p) {
    uint32_t a;
    asm("{ .reg .u64 t; cvta.to.shared.u64 t, %1; cvt.u32.u64 %0, t; }" : "=r"(a) : "l"(p));
    return a;
}

__device__ __forceinline__ void ldsm4(uint32_t& r0, uint32_t& r1, uint32_t& r2, uint32_t& r3,
                                      uint32_t addr) {
    asm volatile("ldmatrix.sync.aligned.m8n8.x4.shared.b16 {%0,%1,%2,%3}, [%4];"
                 : "=r"(r0), "=r"(r1), "=r"(r2), "=r"(r3) : "r"(addr));
}

__device__ __forceinline__ void mma16816(float* d, uint32_t a0, uint32_t a1, uint32_t a2, uint32_t a3,
                                         uint32_t b0, uint32_t b1) {
    asm volatile(
        "mma.sync.aligned.m16n8k16.row.col.f32.f16.f16.f32 "
        "{%0,%1,%2,%3}, {%4,%5,%6,%7}, {%8,%9}, {%0,%1,%2,%3};"
        : "+f"(d[0]), "+f"(d[1]), "+f"(d[2]), "+f"(d[3])
        : "r"(a0), "r"(a1), "r"(a2), "r"(a3), "r"(b0), "r"(b1));
}

// swizzled tile address: 128 rows x 128 halfs (256B rows), 16B chunks XOR'd with row&7
__device__ __forceinline__ uint32_t sw_addr(uint32_t base, int row, int chunk) {
    return base + (uint32_t)row * 256u + (uint32_t)((chunk ^ (row & 7)) << 4);
}

__device__ __forceinline__ uint32_t packh2(__half a, __half b) {
    __half2 h = __halves2half2(a, b);
    return *(uint32_t*)&h;
}

// cp.async 16B
__device__ __forceinline__ void cpasync16(uint32_t dst, const void* src) {
    asm volatile("cp.async.cg.shared.global [%0], [%1], 16;" :: "r"(dst), "l"(src));
}
#define CP_COMMIT()   asm volatile("cp.async.commit_group;" ::: "memory")
#define CP_WAIT_ALL() asm volatile("cp.async.wait_group 0;" ::: "memory")

// cooperative load of a 128x128 half tile into swizzled smem (256 threads, sync path)
__device__ __forceinline__ void load_tile(uint32_t dst, const __half* __restrict__ src,
                                          int row_stride) {
    const int t = threadIdx.x;
#pragma unroll
    for (int i = 0; i < 8; i++) {
        int cid = i * 256 + t;
        int row = cid >> 4, c = cid & 15;
        uint4 v = *(const uint4*)(src + (size_t)row * row_stride + c * 8);
        uint32_t a = sw_addr(dst, row, c);
        asm volatile("st.shared.v4.b32 [%0], {%1, %2, %3, %4};"
                     :: "r"(a), "r"(v.x), "r"(v.y), "r"(v.z), "r"(v.w));
    }
}

// async version (cp.async, caller commits/waits)
__device__ __forceinline__ void load_tile_async(uint32_t dst, const __half* __restrict__ src,
                                                int row_stride) {
    const int t = threadIdx.x;
#pragma unroll
    for (int i = 0; i < 8; i++) {
        int cid = i * 256 + t;
        int row = cid >> 4, c = cid & 15;
        cpasync16(sw_addr(dst, row, c), src + (size_t)row * row_stride + c * 8);
    }
}

// cooperative split-load of a 128x128 fp32 block into swizzled hi/lo fp16 tiles
__device__ __forceinline__ void split_tile(uint32_t dhi, uint32_t dlo,
                                           const float* __restrict__ src, int row_stride) {
    const int t = threadIdx.x;
#pragma unroll
    for (int i = 0; i < 8; i++) {
        int cid = i * 256 + t;
        int row = cid >> 4, c = cid & 15;
        const float* p = src + (size_t)row * row_stride + c * 8;
        float4 v0 = *(const float4*)p;
        float4 v1 = *(const float4*)(p + 4);
        float e[8] = {v0.x, v0.y, v0.z, v0.w, v1.x, v1.y, v1.z, v1.w};
        __half h[8], l[8];
#pragma unroll
        for (int j = 0; j < 8; j++) {
            h[j] = __float2half_rn(e[j]);
            l[j] = __float2half_rn(e[j] - __half2float(h[j]));
        }
        uint32_t hw0 = packh2(h[0], h[1]), hw1 = packh2(h[2], h[3]);
        uint32_t hw2 = packh2(h[4], h[5]), hw3 = packh2(h[6], h[7]);
        uint32_t lw0 = packh2(l[0], l[1]), lw1 = packh2(l[2], l[3]);
        uint32_t lw2 = packh2(l[4], l[5]), lw3 = packh2(l[6], l[7]);
        asm volatile("st.shared.v4.b32 [%0], {%1, %2, %3, %4};"
                     :: "r"(sw_addr(dhi, row, c)), "r"(hw0), "r"(hw1), "r"(hw2), "r"(hw3));
        asm volatile("st.shared.v4.b32 [%0], {%1, %2, %3, %4};"
                     :: "r"(sw_addr(dlo, row, c)), "r"(lw0), "r"(lw1), "r"(lw2), "r"(lw3));
    }
}

// ---------------- Kernel 0: transpose+split x -> [b][n][c] fp16 hi/lo ----------------
__global__ __launch_bounds__(256) void prep_xt_kernel(const float* __restrict__ x)
{
    __shared__ float tile[32][33];
    const int t = threadIdx.x;
    const int tx = t & 31, ty = t >> 5;
    const int b = blockIdx.z;
    const int c0 = blockIdx.y * 32;
    const int n0 = blockIdx.x * 32;
#pragma unroll
    for (int i = 0; i < 4; i++) {
        int c = c0 + ty + i * 8;
        tile[ty + i * 8][tx] = x[(size_t)(b * CIN + c) * NN + n0 + tx];
    }
    __syncthreads();
#pragma unroll
    for (int i = 0; i < 4; i++) {
        int n = n0 + ty + i * 8;
        float v = tile[tx][ty + i * 8];
        __half h = __float2half_rn(v);
        __half l = __float2half_rn(v - __half2float(h));
        size_t idx = (size_t)(b * NN + n) * CIN + c0 + tx;
        d_xt_hi[idx] = h;
        d_xt_lo[idx] = l;
    }
}

// ---------------- Kernel 1: tensor-core projection GEMM ----------------
#define TG_A_HI 0
#define TG_A_LO 32768
#define TG_B_HI 65536
#define TG_B_LO 98304
#define TG_SMEM_BYTES 131072

__global__ __launch_bounds__(256, 1) void proj_tc_kernel(
    const float* __restrict__ gw, const float* __restrict__ gb,
    const float* __restrict__ thw, const float* __restrict__ thb,
    const float* __restrict__ phw, const float* __restrict__ phb)
{
    extern __shared__ char smem[];
    const uint32_t sb = smem_u32(smem);
    const int t = threadIdx.x;
    const int lane = t & 31, w = t >> 5;
    const int b = blockIdx.z;
    const int m0 = blockIdx.y * 128;     // 0 / 128 / 256
    const int n0 = blockIdx.x * 128;

    const float* wsrc;
    const float* bsrc;
    if (m0 == 0)        { wsrc = gw;  bsrc = gb;  }
    else if (m0 == 128) { wsrc = thw; bsrc = thb; }
    else                { wsrc = phw; bsrc = phb; }

    const int frow = lane & 15, fhalf = lane >> 4;
    const int arow = w * 16 + frow;

    float acc[16][4];
#pragma unroll
    for (int nf = 0; nf < 16; nf++)
#pragma unroll
        for (int j = 0; j < 4; j++) acc[nf][j] = 0.0f;

#pragma unroll 1
    for (int k0 = 0; k0 < CIN; k0 += 128) {
        __syncthreads();
        split_tile(sb + TG_A_HI, sb + TG_A_LO, wsrc + k0, CIN);
        load_tile(sb + TG_B_HI, d_xt_hi + (size_t)(b * NN + n0) * CIN + k0, CIN);
        load_tile(sb + TG_B_LO, d_xt_lo + (size_t)(b * NN + n0) * CIN + k0, CIN);
        __syncthreads();

#pragma unroll 1
        for (int kk = 0; kk < 8; kk++) {
            uint32_t ah[4], al[4];
            ldsm4(ah[0], ah[1], ah[2], ah[3], sw_addr(sb + TG_A_HI, arow, kk * 2 + fhalf));
            ldsm4(al[0], al[1], al[2], al[3], sw_addr(sb + TG_A_LO, arow, kk * 2 + fhalf));
#pragma unroll
            for (int np = 0; np < 8; np++) {
                uint32_t bh[4], bl[4];
                ldsm4(bh[0], bh[1], bh[2], bh[3], sw_addr(sb + TG_B_HI, np * 16 + frow, kk * 2 + fhalf));
                ldsm4(bl[0], bl[1], bl[2], bl[3], sw_addr(sb + TG_B_LO, np * 16 + frow, kk * 2 + fhalf));
                mma16816(acc[2 * np],     ah[0], ah[1], ah[2], ah[3], bh[0], bh[2]);
                mma16816(acc[2 * np + 1], ah[0], ah[1], ah[2], ah[3], bh[1], bh[3]);
                mma16816(acc[2 * np],     ah[0], ah[1], ah[2], ah[3], bl[0], bl[2]);
                mma16816(acc[2 * np + 1], ah[0], ah[1], ah[2], ah[3], bl[1], bl[3]);
                mma16816(acc[2 * np],     al[0], al[1], al[2], al[3], bh[0], bh[2]);
                mma16816(acc[2 * np + 1], al[0], al[1], al[2], al[3], bh[1], bh[3]);
            }
        }
    }

    const int r0 = w * 16 + (lane >> 2);
    const float bias0 = bsrc[r0];
    const float bias1 = bsrc[r0 + 8];
    float* out0 = d_proj + (size_t)(m0 + r0) * (BB * NN) + (size_t)b * NN + n0;
    float* out1 = d_proj + (size_t)(m0 + r0 + 8) * (BB * NN) + (size_t)b * NN + n0;
#pragma unroll
    for (int nf = 0; nf < 16; nf++) {
        int n = nf * 8 + (lane & 3) * 2;
        *(float2*)(out0 + n) = make_float2(acc[nf][0] + bias0, acc[nf][1] + bias0);
        *(float2*)(out1 + n) = make_float2(acc[nf][2] + bias1, acc[nf][3] + bias1);
    }
}

// ---------------- Kernel 2: BN stats for projections ----------------
__global__ __launch_bounds__(256) void bn_stats_proj_kernel(
    const float* __restrict__ g_gamma, const float* __restrict__ g_beta,
    const float* __restrict__ th_gamma, const float* __restrict__ th_beta,
    const float* __restrict__ ph_gamma, const float* __restrict__ ph_beta)
{
    __shared__ double ssum[256];
    __shared__ double ssq[256];
    const int ch = blockIdx.x;
    const int t = threadIdx.x;
    const float* base = d_proj + ch * (BB * NN);
    double s = 0.0, q = 0.0;
    for (int i = t; i < BB * NN; i += 256) {
        float v = base[i];
        s += (double)v;
        q += (double)v * (double)v;
    }
    ssum[t] = s; ssq[t] = q;
    __syncthreads();
    for (int off = 128; off > 0; off >>= 1) {
        if (t < off) { ssum[t] += ssum[t + off]; ssq[t] += ssq[t + off]; }
        __syncthreads();
    }
    if (t == 0) {
        double mean = ssum[0] / (double)(BB * NN);
        double var = ssq[0] / (double)(BB * NN) - mean * mean;
        float gamma, beta;
        if (ch < 128)      { gamma = g_gamma[ch];        beta = g_beta[ch]; }
        else if (ch < 256) { gamma = th_gamma[ch - 128]; beta = th_beta[ch - 128]; }
        else               { gamma = ph_gamma[ch - 256]; beta = ph_beta[ch - 256]; }
        float sc = gamma / sqrtf((float)var + BN_EPS);
        d_pscale[ch] = sc;
        d_pshift[ch] = beta - (float)mean * sc;
    }
}

// ---------------- Kernel 2b: prep theta/phi -> fp16 hi/lo, transposed to [b][n][c] ----------------
__global__ __launch_bounds__(256) void prep_qk_kernel()
{
    __shared__ float tile[32][33];
    const int t = threadIdx.x;
    const int tx = t & 31, ty = t >> 5;
    const int sel = blockIdx.z >> 2;      // 0: theta, 1: phi
    const int b = blockIdx.z & 3;
    const int c0 = blockIdx.y * 32;
    const int n0 = blockIdx.x * 32;
    const int chbase = 128 + sel * 128;
#pragma unroll
    for (int i = 0; i < 4; i++) {
        int c = c0 + ty + i * 8;
        float v = d_proj[(size_t)(chbase + c) * (BB * NN) + (size_t)b * NN + n0 + tx];
        tile[ty + i * 8][tx] = v * d_pscale[chbase + c] + d_pshift[chbase + c];
    }
    __syncthreads();
    __half* hi = sel ? d_ph_hi : d_th_hi;
    __half* lo = sel ? d_ph_lo : d_th_lo;
#pragma unroll
    for (int i = 0; i < 4; i++) {
        int n = n0 + ty + i * 8;
        float v = tile[tx][ty + i * 8];
        __half h = __float2half_rn(v);
        __half l = __float2half_rn(v - __half2float(h));
        size_t idx = (size_t)(b * NN + n) * CI + c0 + tx;
        hi[idx] = h;
        lo[idx] = l;
    }
}

// ---------------- Kernel 2c: prep g -> fp16 hi, [b][c][n] ----------------
__global__ __launch_bounds__(256) void prep_g_kernel()
{
    int i = blockIdx.x * 256 + threadIdx.x;  // over BB*CI*NN/4
    int n4 = i & (NN / 4 - 1);
    int rest = i / (NN / 4);
    int c = rest & (CI - 1);
    int b = rest >> 7;
    float4 v = *(const float4*)&d_proj[(size_t)c * (BB * NN) + (size_t)b * NN + n4 * 4];
    float sc = d_pscale[c], sh = d_pshift[c];
    float a0 = v.x * sc + sh, a1 = v.y * sc + sh, a2 = v.z * sc + sh, a3 = v.w * sc + sh;
    __half h0 = __float2half_rn(a0), h1 = __float2half_rn(a1);
    __half h2 = __float2half_rn(a2), h3 = __float2half_rn(a3);
    size_t base = (size_t)(b * CI + c) * NN + n4 * 4;
    *(__half2*)&d_g_hi[base]     = __halves2half2(h0, h1);
    *(__half2*)&d_g_hi[base + 2] = __halves2half2(h2, h3);
}

// ---------------- Kernel 3: pipelined mma.sync flash attention ----------------
// Q_hi in registers; K hi/lo + G hi double-buffered with cp.async prefetch.
// SMEM: QLO[0,32K) KHI0[32K) KLO0[64K) GHI0[96K) KHI1[128K) KLO1[160K) GHI1[192K)
#define A_QLO 0
#define A_KHI0 32768
#define A_KLO0 65536
#define A_GHI0 98304
#define A_KHI1 131072
#define A_KLO1 163840
#define A_GHI1 196608
#define ATTN_SMEM_BYTES 229376

__global__ __launch_bounds__(256, 1) void attn_mma_kernel()
{
    extern __shared__ char smem[];
    const uint32_t sb = smem_u32(smem);
    const int tid = threadIdx.x;
    const int lane = tid & 31;
    const int w = tid >> 5;
    const int b = blockIdx.y;
    const int n0 = blockIdx.x * 128;

    const int frow = lane & 15;
    const int fhalf = lane >> 4;
    const int arow = w * 16 + frow;

    const uint32_t KHI[2] = {sb + A_KHI0, sb + A_KHI1};
    const uint32_t KLO[2] = {sb + A_KLO0, sb + A_KLO1};
    const uint32_t GHI[2] = {sb + A_GHI0, sb + A_GHI1};

    // Prologue: stage Qhi in KHI0, Qlo in QLO
    load_tile_async(KHI[0], d_th_hi + (size_t)(b * NN + n0) * CI, CI);
    load_tile_async(sb + A_QLO, d_th_lo + (size_t)(b * NN + n0) * CI, CI);
    CP_COMMIT();
    CP_WAIT_ALL();
    __syncthreads();

    // Qhi fragments -> registers
    uint32_t qh[8][4];
#pragma unroll
    for (int kk = 0; kk < 8; kk++)
        ldsm4(qh[kk][0], qh[kk][1], qh[kk][2], qh[kk][3], sw_addr(KHI[0], arow, kk * 2 + fhalf));
    __syncthreads();   // staging free

    // Prefetch tile 0
    load_tile_async(KHI[0], d_ph_hi + (size_t)(b * NN) * CI, CI);
    load_tile_async(KLO[0], d_ph_lo + (size_t)(b * NN) * CI, CI);
    load_tile_async(GHI[0], d_g_hi + (size_t)b * CI * NN, NN);
    CP_COMMIT();

    float o[16][4];
#pragma unroll
    for (int nf = 0; nf < 16; nf++)
#pragma unroll
        for (int j = 0; j < 4; j++) o[nf][j] = 0.0f;
    float mr0 = -INFINITY, mr1 = -INFINITY, lr0 = 0.0f, lr1 = 0.0f;

#pragma unroll 1
    for (int t = 0; t < NTILES; t++) {
        const int cur = t & 1, nxt = cur ^ 1;
        CP_WAIT_ALL();
        __syncthreads();
        if (t + 1 < NTILES) {
            const int m1 = (t + 1) * 128;
            load_tile_async(KHI[nxt], d_ph_hi + (size_t)(b * NN + m1) * CI, CI);
            load_tile_async(KLO[nxt], d_ph_lo + (size_t)(b * NN + m1) * CI, CI);
            load_tile_async(GHI[nxt], d_g_hi + (size_t)b * CI * NN + m1, NN);
            CP_COMMIT();
        }

        // ---- S = Qh*Kh^T + Qh*Kl^T + Ql*Kh^T ----
        float s[16][4];
#pragma unroll
        for (int nf = 0; nf < 16; nf++)
#pragma unroll
            for (int j = 0; j < 4; j++) s[nf][j] = 0.0f;

#pragma unroll 1
        for (int kk = 0; kk < 8; kk++) {
            uint32_t ql[4];
            ldsm4(ql[0], ql[1], ql[2], ql[3], sw_addr(sb + A_QLO, arow, kk * 2 + fhalf));
#pragma unroll
            for (int np = 0; np < 8; np++) {
                uint32_t kh[4], kl[4];
                ldsm4(kh[0], kh[1], kh[2], kh[3], sw_addr(KHI[cur], np * 16 + frow, kk * 2 + fhalf));
                ldsm4(kl[0], kl[1], kl[2], kl[3], sw_addr(KLO[cur], np * 16 + frow, kk * 2 + fhalf));
                mma16816(s[2 * np],     qh[kk][0], qh[kk][1], qh[kk][2], qh[kk][3], kh[0], kh[2]);
                mma16816(s[2 * np + 1], qh[kk][0], qh[kk][1], qh[kk][2], qh[kk][3], kh[1], kh[3]);
                mma16816(s[2 * np],     qh[kk][0], qh[kk][1], qh[kk][2], qh[kk][3], kl[0], kl[2]);
                mma16816(s[2 * np + 1], qh[kk][0], qh[kk][1], qh[kk][2], qh[kk][3], kl[1], kl[3]);
                mma16816(s[2 * np],     ql[0], ql[1], ql[2], ql[3], kh[0], kh[2]);
                mma16816(s[2 * np + 1], ql[0], ql[1], ql[2], ql[3], kh[1], kh[3]);
            }
        }

        // ---- online softmax ----
        float tm0 = -INFINITY, tm1 = -INFINITY;
#pragma unroll
        for (int nf = 0; nf < 16; nf++) {
            tm0 = fmaxf(tm0, fmaxf(s[nf][0], s[nf][1]));
            tm1 = fmaxf(tm1, fmaxf(s[nf][2], s[nf][3]));
        }
        tm0 = fmaxf(tm0, __shfl_xor_sync(0xffffffffu, tm0, 1));
        tm0 = fmaxf(tm0, __shfl_xor_sync(0xffffffffu, tm0, 2));
        tm1 = fmaxf(tm1, __shfl_xor_sync(0xffffffffu, tm1, 1));
        tm1 = fmaxf(tm1, __shfl_xor_sync(0xffffffffu, tm1, 2));
        float mn0 = fmaxf(mr0, tm0), mn1 = fmaxf(mr1, tm1);
        float c0 = __expf(mr0 - mn0), c1 = __expf(mr1 - mn1);
        mr0 = mn0; mr1 = mn1;

        uint32_t ph[16][2];
        float rs0 = 0.0f, rs1 = 0.0f;
#pragma unroll
        for (int nf = 0; nf < 16; nf++) {
            float p0 = __expf(s[nf][0] - mn0);
            float p1 = __expf(s[nf][1] - mn0);
            float p2 = __expf(s[nf][2] - mn1);
            float p3 = __expf(s[nf][3] - mn1);
            rs0 += p0 + p1; rs1 += p2 + p3;
            __half2 h01 = __floats2half2_rn(p0, p1);
            __half2 h23 = __floats2half2_rn(p2, p3);
            ph[nf][0] = *(uint32_t*)&h01;
            ph[nf][1] = *(uint32_t*)&h23;
        }
        rs0 += __shfl_xor_sync(0xffffffffu, rs0, 1);
        rs0 += __shfl_xor_sync(0xffffffffu, rs0, 2);
        rs1 += __shfl_xor_sync(0xffffffffu, rs1, 1);
        rs1 += __shfl_xor_sync(0xffffffffu, rs1, 2);
        lr0 = lr0 * c0 + rs0;
        lr1 = lr1 * c1 + rs1;
#pragma unroll
        for (int nf = 0; nf < 16; nf++) {
            o[nf][0] *= c0; o[nf][1] *= c0; o[nf][2] *= c1; o[nf][3] *= c1;
        }

        // ---- O += P * Ghi^T ----
#pragma unroll 1
        for (int kk = 0; kk < 8; kk++) {
            uint32_t a0 = ph[2 * kk][0], a1 = ph[2 * kk][1];
            uint32_t a2 = ph[2 * kk + 1][0], a3 = ph[2 * kk + 1][1];
#pragma unroll
            for (int np = 0; np < 8; np++) {
                uint32_t gh[4];
                ldsm4(gh[0], gh[1], gh[2], gh[3], sw_addr(GHI[cur], np * 16 + frow, kk * 2 + fhalf));
                mma16816(o[2 * np],     a0, a1, a2, a3, gh[0], gh[2]);
                mma16816(o[2 * np + 1], a0, a1, a2, a3, gh[1], gh[3]);
            }
        }
    }

    // epilogue: y = O / l, split hi/lo, store directly as [b][n][c] fp16
    const float inv0 = 1.0f / lr0, inv1 = 1.0f / lr1;
    const int q0 = n0 + w * 16 + (lane >> 2);
    __half* yh0 = d_y_hi + (size_t)(b * NN + q0) * CI;
    __half* yl0 = d_y_lo + (size_t)(b * NN + q0) * CI;
    __half* yh1 = d_y_hi + (size_t)(b * NN + q0 + 8) * CI;
    __half* yl1 = d_y_lo + (size_t)(b * NN + q0 + 8) * CI;
#pragma unroll
    for (int nf = 0; nf < 16; nf++) {
        int c = nf * 8 + (lane & 3) * 2;
        float v0 = o[nf][0] * inv0, v1 = o[nf][1] * inv0;
        float v2 = o[nf][2] * inv1, v3 = o[nf][3] * inv1;
        __half h0 = __float2half_rn(v0), h1 = __float2half_rn(v1);
        __half h2 = __float2half_rn(v2), h3 = __float2half_rn(v3);
        *(__half2*)(yh0 + c) = __halves2half2(h0, h1);
        *(__half2*)(yl0 + c) = __halves2half2(__float2half_rn(v0 - __half2float(h0)),
                                              __float2half_rn(v1 - __half2float(h1)));
        *(__half2*)(yh1 + c) = __halves2half2(h2, h3);
        *(__half2*)(yl1 + c) = __halves2half2(__float2half_rn(v2 - __half2float(h2)),
                                              __float2half_rn(v3 - __half2float(h3)));
    }
}

// ---------------- Kernel 4: tensor-core W GEMM + bias + residual ----------------
__global__ __launch_bounds__(256, 1) void wgemm_tc_kernel(
    const float* __restrict__ x,
    const float* __restrict__ Ww, const float* __restrict__ Wb)
{
    extern __shared__ char smem[];
    const uint32_t sb = smem_u32(smem);
    const int t = threadIdx.x;
    const int lane = t & 31, w = t >> 5;
    const int b = blockIdx.z;
    const int o0 = blockIdx.y * 128;
    const int n0 = blockIdx.x * 128;

    const int frow = lane & 15, fhalf = lane >> 4;
    const int arow = w * 16 + frow;

    split_tile(sb + TG_A_HI, sb + TG_A_LO, Ww + (size_t)o0 * CI, CI);
    load_tile(sb + TG_B_HI, d_y_hi + (size_t)(b * NN + n0) * CI, CI);
    load_tile(sb + TG_B_LO, d_y_lo + (size_t)(b * NN + n0) * CI, CI);
    __syncthreads();

    float acc[16][4];
#pragma unroll
    for (int nf = 0; nf < 16; nf++)
#pragma unroll
        for (int j = 0; j < 4; j++) acc[nf][j] = 0.0f;

#pragma unroll 1
    for (int kk = 0; kk < 8; kk++) {
        uint32_t ah[4], al[4];
        ldsm4(ah[0], ah[1], ah[2], ah[3], sw_addr(sb + TG_A_HI, arow, kk * 2 + fhalf));
        ldsm4(al[0], al[1], al[2], al[3], sw_addr(sb + TG_A_LO, arow, kk * 2 + fhalf));
#pragma unroll
        for (int np = 0; np < 8; np++) {
            uint32_t bh[4], bl[4];
            ldsm4(bh[0], bh[1], bh[2], bh[3], sw_addr(sb + TG_B_HI, np * 16 + frow, kk * 2 + fhalf));
            ldsm4(bl[0], bl[1], bl[2], bl[3], sw_addr(sb + TG_B_LO, np * 16 + frow, kk * 2 + fhalf));
            mma16816(acc[2 * np],     ah[0], ah[1], ah[2], ah[3], bh[0], bh[2]);
            mma16816(acc[2 * np + 1], ah[0], ah[1], ah[2], ah[3], bh[1], bh[3]);
            mma16816(acc[2 * np],     ah[0], ah[1], ah[2], ah[3], bl[0], bl[2]);
            mma16816(acc[2 * np + 1], ah[0], ah[1], ah[2], ah[3], bl[1], bl[3]);
            mma16816(acc[2 * np],     al[0], al[1], al[2], al[3], bh[0], bh[2]);
            mma16816(acc[2 * np + 1], al[0], al[1], al[2], al[3], bh[1], bh[3]);
        }
    }

    const int r0 = o0 + w * 16 + (lane >> 2);
    const float bias0 = Wb[r0], bias1 = Wb[r0 + 8];
    const float* xr0 = x + (size_t)(b * COUT + r0) * NN + n0;
    const float* xr1 = x + (size_t)(b * COUT + r0 + 8) * NN + n0;
    float* z0 = d_z + (size_t)r0 * (BB * NN) + (size_t)b * NN + n0;
    float* z1 = d_z + (size_t)(r0 + 8) * (BB * NN) + (size_t)b * NN + n0;
#pragma unroll
    for (int nf = 0; nf < 16; nf++) {
        int n = nf * 8 + (lane & 3) * 2;
        float2 xa = *(const float2*)(xr0 + n);
        float2 xb = *(const float2*)(xr1 + n);
        *(float2*)(z0 + n) = make_float2(acc[nf][0] + bias0 + xa.x, acc[nf][1] + bias0 + xa.y);
        *(float2*)(z1 + n) = make_float2(acc[nf][2] + bias1 + xb.x, acc[nf][3] + bias1 + xb.y);
    }
}

// ---------------- Kernel 5: BN stats for z ----------------
__global__ __launch_bounds__(256) void bn_stats_z_kernel(
    const float* __restrict__ bn_gamma, const float* __restrict__ bn_beta)
{
    __shared__ double ssum[256];
    __shared__ double ssq[256];
    const int ch = blockIdx.x;
    const int t = threadIdx.x;
    const float* base = d_z + ch * (BB * NN);
    double s = 0.0, q = 0.0;
    for (int i = t; i < BB * NN; i += 256) {
        float v = base[i];
        s += (double)v;
        q += (double)v * (double)v;
    }
    ssum[t] = s; ssq[t] = q;
    __syncthreads();
    for (int off = 128; off > 0; off >>= 1) {
        if (t < off) { ssum[t] += ssum[t + off]; ssq[t] += ssq[t + off]; }
        __syncthreads();
    }
    if (t == 0) {
        double mean = ssum[0] / (double)(BB * NN);
        double var = ssq[0] / (double)(BB * NN) - mean * mean;
        float sc = bn_gamma[ch] / sqrtf((float)var + BN_EPS);
        d_zscale[ch] = sc;
        d_zshift[ch] = bn_beta[ch] - (float)mean * sc;
    }
}

// ---------------- Kernel 6: final normalize ----------------
__global__ __launch_bounds__(256) void finalize_kernel(float* __restrict__ out)
{
    int idx = blockIdx.x * 256 + threadIdx.x;
    int o = idx >> 14;
    int rem = idx & 16383;
    int b = rem >> 12;
    int n = rem & 4095;
    out[(b * COUT + o) * NN + n] = d_z[idx] * d_zscale[o] + d_zshift[o];
}

// ---------------- host launcher ----------------
extern "C" void kernel_launch(void* const* d_in, const int* in_sizes, int n_in,
                              void* d_out, int out_size)
{
    const float* x        = (const float*)d_in[0];
    const float* g_w      = (const float*)d_in[1];
    const float* g_b      = (const float*)d_in[2];
    const float* g_gamma  = (const float*)d_in[3];
    const float* g_beta   = (const float*)d_in[4];
    const float* th_w     = (const float*)d_in[5];
    const float* th_b     = (const float*)d_in[6];
    const float* th_gamma = (const float*)d_in[7];
    const float* th_beta  = (const float*)d_in[8];
    const float* ph_w     = (const float*)d_in[9];
    const float* ph_b     = (const float*)d_in[10];
    const float* ph_gamma = (const float*)d_in[11];
    const float* ph_beta  = (const float*)d_in[12];
    const float* W_w      = (const float*)d_in[13];
    const float* W_b      = (const float*)d_in[14];
    const float* bn_gamma = (const float*)d_in[15];
    const float* bn_beta  = (const float*)d_in[16];
    float* out = (float*)d_out;

    cudaFuncSetAttribute(proj_tc_kernel, cudaFuncAttributeMaxDynamicSharedMemorySize, TG_SMEM_BYTES);
    cudaFuncSetAttribute(wgemm_tc_kernel, cudaFuncAttributeMaxDynamicSharedMemorySize, TG_SMEM_BYTES);
    cudaFuncSetAttribute(attn_mma_kernel, cudaFuncAttributeMaxDynamicSharedMemorySize, ATTN_SMEM_BYTES);

    prep_xt_kernel<<<dim3(NN / 32, CIN / 32, BB), 256>>>(x);
    proj_tc_kernel<<<dim3(NN / 128, CP / 128, BB), 256, TG_SMEM_BYTES>>>(
        g_w, g_b, th_w, th_b, ph_w, ph_b);
    bn_stats_proj_kernel<<<CP, 256>>>(g_gamma, g_beta, th_gamma, th_beta, ph_gamma, ph_beta);
    prep_qk_kernel<<<dim3(NN / 32, CI / 32, BB * 2), 256>>>();
    prep_g_kernel<<<(BB * CI * NN / 4) / 256, 256>>>();
    attn_mma_kernel<<<dim3(NTILES, BB), 256, ATTN_SMEM_BYTES>>>();
    wgemm_tc_kernel<<<dim3(NN / 128, COUT / 128, BB), 256, TG_SMEM_BYTES>>>(x, W_w, W_b);
    bn_stats_z_kernel<<<COUT, 256>>>(bn_gamma, bn_beta);
    finalize_kernel<<<(COUT * BB * NN) / 256, 256>>>(out);
}